// round 9
// baseline (speedup 1.0000x reference)
#include <cuda_runtime.h>
#include <cuda_fp16.h>
#include <math.h>
#include <cstdint>

#define NN   4096
#define KK   16
#define DIMM 256
#define RR   8192
#define GD   8

// ---- device scratch (static, no allocation) ----
__device__ int   g_hist[17];
__device__ int   g_off[17];
__device__ int   g_cnt[16];
__device__ int   g_sorted_orig[NN];
__device__ int   g_sorted_len[NN];
__device__ float g_Wx[NN * 1024];
__device__ float g_C[GD][NN * DIMM];           // c state fp32
__device__ __half g_Yf16[2][NN * KK * DIMM];   // gate-0 fwd/bwd seq outputs (fp16)
__device__ __half g_Hfin[GD][NN * DIMM];       // final h per gd (fp16)
__device__ float g_fseq[NN * KK * DIMM];       // fc0 projection of ycat
__device__ float g_ydot[3 * NN * DIMM];        // fc1..3 projections of y_last
// fp16 h/H state + weights
__device__ __half g_hf16[RR * DIMM];            // h_tensor (rounded)
__device__ __half g_Hf16[2][GD][NN * DIMM];     // H state (double buffered)
// packed weights: [gd][ntile4][chunk8] blocks of 256 n-rows x 64 k halves (K-major BT)
__device__ __half g_Bpf[8u * 4u * 8u * 16384u];
// packed fc weights: [gate4][256 n][512 k] fp16 (BT, K-major)
__device__ __half g_fcp[4u * 256u * 512u];

__device__ __forceinline__ float sigm(float x) { return 1.f / (1.f + expf(-x)); }

// ---- PTX helpers (non-'a' features only: cp.async, ldmatrix, mma.sync) ----
__device__ __forceinline__ uint32_t smem_u32(const void* p) {
    uint32_t a;
    asm("{ .reg .u64 t; cvta.to.shared.u64 t, %1; cvt.u32.u64 %0, t; }" : "=r"(a) : "l"(p));
    return a;
}
#define CP_ASYNC16(dst, src) \
    asm volatile("cp.async.cg.shared.global [%0], [%1], 16;" :: "r"(dst), "l"(src))
#define CP_COMMIT() asm volatile("cp.async.commit_group;" ::: "memory")
#define CP_WAIT(n)  asm volatile("cp.async.wait_group %0;" :: "n"(n) : "memory")

__device__ __forceinline__ void ldsm4(uint32_t* r, uint32_t addr) {
    asm volatile("ldmatrix.sync.aligned.m8n8.x4.shared.b16 {%0,%1,%2,%3}, [%4];"
                 : "=r"(r[0]), "=r"(r[1]), "=r"(r[2]), "=r"(r[3]) : "r"(addr));
}
__device__ __forceinline__ void mma_f16(float* c, const uint32_t* a, const uint32_t* b) {
    asm volatile("mma.sync.aligned.m16n8k16.row.col.f32.f16.f16.f32 "
                 "{%0,%1,%2,%3}, {%4,%5,%6,%7}, {%8,%9}, {%0,%1,%2,%3};"
                 : "+f"(c[0]), "+f"(c[1]), "+f"(c[2]), "+f"(c[3])
                 : "r"(a[0]), "r"(a[1]), "r"(a[2]), "r"(a[3]), "r"(b[0]), "r"(b[1]));
}

// ---------------- sorting by length (desc) ----------------
__global__ void zero_hist_kernel() { if (threadIdx.x < 17) g_hist[threadIdx.x] = 0; }

__global__ void len_hist_kernel(const int* __restrict__ indice) {
    int n = blockIdx.x * blockDim.x + threadIdx.x;
    if (n >= NN) return;
    int len = 0;
#pragma unroll
    for (int k = 0; k < KK; k++) len += (indice[n * KK + k] != -1);
    atomicAdd(&g_hist[len], 1);
}

__global__ void prefix_kernel() {
    if (threadIdx.x != 0 || blockIdx.x != 0) return;
    int run = 0;
    for (int l = 16; l >= 1; l--) { g_off[l] = run; run += g_hist[l]; }
    for (int t = 0; t < 16; t++) g_cnt[t] = g_off[t + 1] + g_hist[t + 1];
}

__global__ void scatter_kernel(const int* __restrict__ indice) {
    int n = blockIdx.x * blockDim.x + threadIdx.x;
    if (n >= NN) return;
    int len = 0;
#pragma unroll
    for (int k = 0; k < KK; k++) len += (indice[n * KK + k] != -1);
    int pos = atomicAdd(&g_off[len], 1);
    g_sorted_orig[pos] = n;
    g_sorted_len[pos]  = len;
}

// ------- prep: round h_tensor, pack weights (lstm + fc), init states -------
__global__ void prep_kernel(const float* __restrict__ ih, const float* __restrict__ ic,
                            const float* __restrict__ lk, const float* __restrict__ lr,
                            const float* __restrict__ h_tensor,
                            const float* __restrict__ fc_w) {
    int idx = blockIdx.x * blockDim.x + threadIdx.x;
    if (idx < RR * DIMM) {           // h_tensor round
        g_hf16[idx] = __float2half(h_tensor[idx]);
    }
    if (idx < 8 * 512 * 1024) {      // lstm weight pack: gate-interleaved, K-major BT blocks
        int gd = idx >> 19;
        int rem = idx & ((1 << 19) - 1);
        int kg = rem >> 10;          // 0..511
        int pc = rem & 1023;         // packed col: 4*j + q (q: 0=i,1=f,2=u,3=o)
        int oc = (pc & 3) * 256 + (pc >> 2);
        float w = (kg < 256) ? lk[((size_t)gd * 256 + kg) * 1024 + oc]
                             : lr[((size_t)gd * 256 + (kg - 256)) * 1024 + oc];
        int ntile = pc >> 8;         // 4 tiles of 256 packed cols
        int n     = pc & 255;
        int chunk = kg >> 6;
        int k     = kg & 63;
        size_t dst = ((size_t)(gd * 4 + ntile) * 8 + chunk) * 16384u + (size_t)n * 64 + k;
        g_Bpf[dst] = __float2half(w);
    }
    if (idx < 4 * 256 * 512) {       // fc weight pack: BT [gate][n][k]
        int g = idx >> 17;
        int rem = idx & ((1 << 17) - 1);
        int n = rem >> 9, k = rem & 511;
        g_fcp[idx] = __float2half(fc_w[((size_t)g * 512 + k) * 256 + n]);
    }
    if (idx < GD * NN * DIMM) {      // init H + C
        int j  = idx & (DIMM - 1);
        int gd = idx / (NN * DIMM);
        int r  = idx % (NN * DIMM);
        g_Hf16[0][gd][r] = __float2half(ih[gd * DIMM + j]);
        g_C[gd][r] = ic[gd * DIMM + j];
    }
}

// ---------------- W_x = x @ W_w + W_b ----------------
__global__ __launch_bounds__(256) void wx_gemm_kernel(
    const float* __restrict__ A, const float* __restrict__ B, const float* __restrict__ bias) {
    int m0 = blockIdx.x * 64, n0 = blockIdx.y * 64;
    int tid = threadIdx.x, tx = tid & 15, ty = tid >> 4;
    __shared__ __align__(16) float As[32][68];
    __shared__ __align__(16) float Bs[32][64];
    float acc[4][4];
#pragma unroll
    for (int u = 0; u < 4; u++) {
        float b = bias[n0 + tx * 4 + u];
#pragma unroll
        for (int i = 0; i < 4; i++) acc[i][u] = b;
    }
    for (int kb = 0; kb < 8; kb++) {
        int k0 = kb * 32;
        {
            int row = tid >> 2; int kp = (tid & 3) * 8;
            float4 v0 = *(const float4*)(A + (m0 + row) * 256 + k0 + kp);
            float4 v1 = *(const float4*)(A + (m0 + row) * 256 + k0 + kp + 4);
            As[kp + 0][row] = v0.x; As[kp + 1][row] = v0.y; As[kp + 2][row] = v0.z; As[kp + 3][row] = v0.w;
            As[kp + 4][row] = v1.x; As[kp + 5][row] = v1.y; As[kp + 6][row] = v1.z; As[kp + 7][row] = v1.w;
        }
#pragma unroll
        for (int jj = 0; jj < 8; jj++) {
            int l = tid + 256 * jj; int k = l >> 6; int c = l & 63;
            Bs[k][c] = B[(k0 + k) * 1024 + n0 + c];
        }
        __syncthreads();
#pragma unroll
        for (int kk = 0; kk < 32; kk++) {
            float4 av = *(const float4*)&As[kk][ty * 4];
            float4 bv = *(const float4*)&Bs[kk][tx * 4];
            float a[4] = {av.x, av.y, av.z, av.w};
            float b[4] = {bv.x, bv.y, bv.z, bv.w};
#pragma unroll
            for (int i = 0; i < 4; i++)
#pragma unroll
                for (int u = 0; u < 4; u++) acc[i][u] = fmaf(a[i], b[u], acc[i][u]);
        }
        __syncthreads();
    }
#pragma unroll
    for (int i = 0; i < 4; i++) {
        float4 v = make_float4(acc[i][0], acc[i][1], acc[i][2], acc[i][3]);
        *(float4*)&g_Wx[(m0 + ty * 4 + i) * 1024 + n0 + tx * 4] = v;
    }
}

// ---- HMMA recurrent step: CTA 128x256, 8 warps, warp 64x64, fp16, 3-deep pipe ----
#define SPA       18432                    // 128 rows x 144B
#define SPB       36864                    // 256 rows x 144B
#define BUF_B     (SPA + SPB)              // 55296
#define SM_CHILD  (3 * BUF_B)              // 165888
#define SMEM_STEP (3 * BUF_B + 512)        // 166400
#define NT        512                      // fc gemm kernel threads

__global__ __launch_bounds__(256, 1) void step_mma_kernel(
    int t, const int* __restrict__ indice, const float* __restrict__ lb) {
    extern __shared__ __align__(1024) char smem[];
    const int gd = blockIdx.z;
    const int ntile = blockIdx.y;            // 0..3 (256 packed cols each)
    const int Mact = g_cnt[t];
    const int m0 = blockIdx.x * 128;
    if (m0 >= Mact) return;
    const int tid = threadIdx.x;
    const int wid = tid >> 5, lane = tid & 31;
    const uint32_t sb = smem_u32(smem);
    int* childs = (int*)(smem + SM_CHILD);

    if (tid < 128) {
        int s = m0 + tid;
        int ci = 0;
        if (s < Mact) {
            int orig = g_sorted_orig[s];
            int len  = g_sorted_len[s];
            int tt = (gd & 1) ? (len - 1 - t) : t;
            ci = indice[orig * KK + tt];
        }
        childs[tid] = ci;
    }
    __syncthreads();

    const __half* Hin = &g_Hf16[t & 1][gd][0];
    const size_t bblk = (size_t)(gd * 4 + ntile) * 8;

    float acc[4][8][4];                      // warp tile 64x64: [mt4][nf8][quad]
#pragma unroll
    for (int mt = 0; mt < 4; mt++)
#pragma unroll
        for (int nf = 0; nf < 8; nf++)
#pragma unroll
            for (int u = 0; u < 4; u++) acc[mt][nf][u] = 0.f;

    const int mw = wid & 1, nw = wid >> 1;   // 2 x 4 warp grid
    const int m0w = mw * 64, n0w = nw * 64;
    const int am = lane >> 3, ar = lane & 7;

    auto stage = [&](int c) {
        uint32_t base = sb + (c % 3) * BUF_B;
        uint32_t aS = base;
        uint32_t bS = base + SPA;
#pragma unroll
        for (int i = 0; i < 4; i++) {       // A: 1024 segs of 16B
            int g = tid + i * 256;
            int row = g >> 3, seg = g & 7;
            const __half* src;
            if (c < 4) src = g_hf16 + (size_t)childs[row] * 256 + c * 64 + seg * 8;
            else       src = Hin + (size_t)(m0 + row) * 256 + (c - 4) * 64 + seg * 8;
            CP_ASYNC16(aS + row * 144 + seg * 16, src);
        }
        const __half* bw = g_Bpf + (bblk + c) * 16384u;
#pragma unroll
        for (int i = 0; i < 8; i++) {       // B: 2048 segs of 16B
            int g = tid + i * 256;
            int row = g >> 3, seg = g & 7;
            CP_ASYNC16(bS + row * 144 + seg * 16, bw + row * 64 + seg * 8);
        }
        CP_COMMIT();
    };

    auto compute = [&](int c) {
        uint32_t base = sb + (c % 3) * BUF_B;
        uint32_t aS = base;
        uint32_t bS = base + SPA;
#pragma unroll
        for (int ks = 0; ks < 4; ks++) {
            int k0 = ks * 16;
            uint32_t af[4][4];
            int arow_off = ((am & 1) ? 8 : 0) + ar;
            int akk = (k0 + ((am >= 2) ? 8 : 0)) * 2;
#pragma unroll
            for (int mt = 0; mt < 4; mt++) {
                uint32_t off = (uint32_t)(m0w + mt * 16 + arow_off) * 144 + akk;
                ldsm4(af[mt], aS + off);
            }
            int brow_off = ((am >= 2) ? 8 : 0) + ar;
            int bkk = (k0 + ((am & 1) ? 8 : 0)) * 2;
#pragma unroll
            for (int np = 0; np < 4; np++) {
                uint32_t off = (uint32_t)(n0w + np * 16 + brow_off) * 144 + bkk;
                uint32_t rb[4];
                ldsm4(rb, bS + off);
                uint32_t b0[2] = {rb[0], rb[1]}, b1[2] = {rb[2], rb[3]};
#pragma unroll
                for (int mt = 0; mt < 4; mt++) {
                    mma_f16(acc[mt][np * 2], af[mt], b0);
                    mma_f16(acc[mt][np * 2 + 1], af[mt], b1);
                }
            }
        }
    };

    stage(0);
    stage(1);
#pragma unroll
    for (int c = 0; c < 8; c++) {
        if (c == 7) { CP_WAIT(0); } else { CP_WAIT(1); }
        __syncthreads();
        if (c + 2 < 8) stage(c + 2);
        compute(c);
    }
    __syncthreads();

    // epilogue: accums -> smem (stride 264), then pointwise LSTM
    float* zs = (float*)smem;    // [128][264]
#pragma unroll
    for (int mt = 0; mt < 4; mt++)
#pragma unroll
        for (int nf = 0; nf < 8; nf++) {
            int row = m0w + mt * 16 + (lane >> 2);
            int col = n0w + nf * 8 + (lane & 3) * 2;
            zs[row * 264 + col]           = acc[mt][nf][0];
            zs[row * 264 + col + 1]       = acc[mt][nf][1];
            zs[(row + 8) * 264 + col]     = acc[mt][nf][2];
            zs[(row + 8) * 264 + col + 1] = acc[mt][nf][3];
        }
    __syncthreads();

    const int dsel = gd & 1;
    const bool isG0 = gd < 2;
    const int par = (t + 1) & 1;
    const int cntNext = (t < 15) ? g_cnt[t + 1] : 0;   // rows with len == t+1: s >= cntNext
#pragma unroll
    for (int i = 0; i < 32; i++) {
        int e = tid + i * 256;              // 128 rows x 64 dims
        int row = e >> 6, d = e & 63;
        int s = m0 + row;
        if (s < Mact) {
            int jb = ntile * 64 + d;
            float zi = zs[row * 264 + 4 * d + 0] + lb[gd * 1024 + jb];
            float zf = zs[row * 264 + 4 * d + 1] + lb[gd * 1024 + 256 + jb];
            float zu = zs[row * 264 + 4 * d + 2] + lb[gd * 1024 + 512 + jb];
            float zo = zs[row * 264 + 4 * d + 3] + lb[gd * 1024 + 768 + jb];
            size_t off = (size_t)s * DIMM + jb;
            float cnew = sigm(zf) * g_C[gd][off] + sigm(zi) * tanhf(zu);
            float hnew = sigm(zo) * tanhf(cnew);
            g_C[gd][off] = cnew;
            __half hh = __float2half(hnew);
            g_Hf16[par][gd][off] = hh;
            if (isG0) g_Yf16[dsel][((size_t)s * KK + t) * DIMM + jb] = hh;
            if (s >= cntNext) g_Hfin[gd][off] = hh;    // t == len-1: final h
        }
    }
}

// ---- generic HMMA fc GEMM: C[M,256] = [A0|A1][M,512] @ Bp^T, 16 warps, 32x64 ----
// mode 0: f_seq (M=NN*KK);  mode g in 1..3: y_last gate g (M=NN)
__global__ __launch_bounds__(NT, 1) void gemm_fc_kernel(int mode) {
    extern __shared__ __align__(1024) char smem[];
    const int m0 = blockIdx.x * 128;
    const int tid = threadIdx.x;
    const int wid = tid >> 5, lane = tid & 31;
    const uint32_t sb = smem_u32(smem);

    const __half *A0, *A1, *Bp;
    float* Cout;
    if (mode == 0) {
        A0 = g_Yf16[0]; A1 = g_Yf16[1];
        Bp = g_fcp; Cout = g_fseq;
    } else {
        A0 = g_Hfin[2 * mode]; A1 = g_Hfin[2 * mode + 1];
        Bp = g_fcp + (size_t)mode * 131072u;
        Cout = g_ydot + (size_t)(mode - 1) * NN * DIMM;
    }

    float acc[2][8][4];
#pragma unroll
    for (int mt = 0; mt < 2; mt++)
#pragma unroll
        for (int nf = 0; nf < 8; nf++)
#pragma unroll
            for (int u = 0; u < 4; u++) acc[mt][nf][u] = 0.f;

    const int mw = wid & 3, nw = wid >> 2;
    const int m0w = mw * 32, n0w = nw * 64;
    const int am = lane >> 3, ar = lane & 7;

    auto stage = [&](int c) {
        uint32_t base = sb + (c % 3) * BUF_B;
        uint32_t aS = base;
        uint32_t bS = base + SPA;
#pragma unroll
        for (int i = 0; i < 2; i++) {
            int g = tid + i * NT;
            int row = g >> 3, seg = g & 7;
            const __half* src = (c < 4)
                ? A0 + (size_t)(m0 + row) * 256 + c * 64 + seg * 8
                : A1 + (size_t)(m0 + row) * 256 + (c - 4) * 64 + seg * 8;
            CP_ASYNC16(aS + row * 144 + seg * 16, src);
        }
#pragma unroll
        for (int i = 0; i < 4; i++) {
            int g = tid + i * NT;
            int row = g >> 3, seg = g & 7;   // row = n index, Bp stride 512
            CP_ASYNC16(bS + row * 144 + seg * 16, Bp + (size_t)row * 512 + c * 64 + seg * 8);
        }
        CP_COMMIT();
    };

    auto compute = [&](int c) {
        uint32_t base = sb + (c % 3) * BUF_B;
        uint32_t aS = base;
        uint32_t bS = base + SPA;
#pragma unroll
        for (int ks = 0; ks < 4; ks++) {
            int k0 = ks * 16;
            uint32_t af[2][4];
            int arow_off = ((am & 1) ? 8 : 0) + ar;
            int akk = (k0 + ((am >= 2) ? 8 : 0)) * 2;
#pragma unroll
            for (int mt = 0; mt < 2; mt++) {
                uint32_t off = (uint32_t)(m0w + mt * 16 + arow_off) * 144 + akk;
                ldsm4(af[mt], aS + off);
            }
            int brow_off = ((am >= 2) ? 8 : 0) + ar;
            int bkk = (k0 + ((am & 1) ? 8 : 0)) * 2;
#pragma unroll
            for (int np = 0; np < 4; np++) {
                uint32_t off = (uint32_t)(n0w + np * 16 + brow_off) * 144 + bkk;
                uint32_t rb[4];
                ldsm4(rb, bS + off);
                uint32_t b0[2] = {rb[0], rb[1]}, b1[2] = {rb[2], rb[3]};
#pragma unroll
                for (int mt = 0; mt < 2; mt++) {
                    mma_f16(acc[mt][np * 2], af[mt], b0);
                    mma_f16(acc[mt][np * 2 + 1], af[mt], b1);
                }
            }
        }
    };

    stage(0);
    stage(1);
#pragma unroll
    for (int c = 0; c < 8; c++) {
        if (c == 7) { CP_WAIT(0); } else { CP_WAIT(1); }
        __syncthreads();
        if (c + 2 < 8) stage(c + 2);
        compute(c);
    }
    __syncthreads();

    float* zs = (float*)smem;    // [128][264]
#pragma unroll
    for (int mt = 0; mt < 2; mt++)
#pragma unroll
        for (int nf = 0; nf < 8; nf++) {
            int row = m0w + mt * 16 + (lane >> 2);
            int col = n0w + nf * 8 + (lane & 3) * 2;
            zs[row * 264 + col]           = acc[mt][nf][0];
            zs[row * 264 + col + 1]       = acc[mt][nf][1];
            zs[(row + 8) * 264 + col]     = acc[mt][nf][2];
            zs[(row + 8) * 264 + col + 1] = acc[mt][nf][3];
        }
    __syncthreads();

#pragma unroll
    for (int i = 0; i < 16; i++) {          // 128 rows x 64 float4s
        int e = tid + i * NT;
        int row = e >> 6, q = e & 63;
        float4 v = make_float4(zs[row * 264 + q * 4], zs[row * 264 + q * 4 + 1],
                               zs[row * 264 + q * 4 + 2], zs[row * 264 + q * 4 + 3]);
        *(float4*)&Cout[(size_t)(m0 + row) * 256 + q * 4] = v;
    }
}

// ---------------- final combine (light) ----------------
__global__ __launch_bounds__(256) void combine_kernel(
    const float* __restrict__ c_tensor, const int* __restrict__ indice,
    float* __restrict__ out) {
    int s = blockIdx.x;
    int j = threadIdx.x;
    int orig = g_sorted_orig[s];
    int len  = g_sorted_len[s];

    __shared__ int ciS[KK];
    if (j < KK) ciS[j] = (j < len) ? indice[orig * KK + j] : 0;
    __syncthreads();

    float Wf = g_Wx[orig * 1024 + j];
    float bf = 0.f;
    for (int t = 0; t < len; t++) {
        float fs = g_fseq[((size_t)s * KK + t) * DIMM + j];
        bf += sigm(Wf + fs) * c_tensor[(size_t)ciS[t] * DIMM + j];
    }

    float d0 = g_ydot[(size_t)0 * NN * DIMM + (size_t)s * DIMM + j];
    float d1 = g_ydot[(size_t)1 * NN * DIMM + (size_t)s * DIMM + j];
    float d2 = g_ydot[(size_t)2 * NN * DIMM + (size_t)s * DIMM + j];

    float Wi = g_Wx[orig * 1024 + 256 + j];
    float Wu = g_Wx[orig * 1024 + 512 + j];
    float Wo = g_Wx[orig * 1024 + 768 + j];
    float bi = sigm(d0 + Wi);
    float bu = tanhf(d1 + Wu);
    float bo = sigm(d2 + Wo);
    float nc = bi * bu + bf;
    float nh = bo * tanhf(nc);
    out[(size_t)orig * DIMM + j] = nh;
    out[(size_t)NN * DIMM + (size_t)orig * DIMM + j] = nc;
}

// ---------------- launch ----------------
extern "C" void kernel_launch(void* const* d_in, const int* in_sizes, int n_in,
                              void* d_out, int out_size) {
    const float* x        = (const float*)d_in[0];
    const float* h_tensor = (const float*)d_in[1];
    const float* c_tensor = (const float*)d_in[2];
    const int*   indice   = (const int*)d_in[3];
    const float* W_w      = (const float*)d_in[4];
    const float* W_b      = (const float*)d_in[5];
    const float* lk       = (const float*)d_in[6];
    const float* lr       = (const float*)d_in[7];
    const float* lb       = (const float*)d_in[8];
    const float* ih       = (const float*)d_in[9];
    const float* ic       = (const float*)d_in[10];
    const float* fc       = (const float*)d_in[11];
    float* out = (float*)d_out;

    cudaFuncSetAttribute(step_mma_kernel, cudaFuncAttributeMaxDynamicSharedMemorySize,
                         SMEM_STEP);
    cudaFuncSetAttribute(gemm_fc_kernel, cudaFuncAttributeMaxDynamicSharedMemorySize,
                         SMEM_STEP);

    zero_hist_kernel<<<1, 32>>>();
    len_hist_kernel<<<NN / 256, 256>>>(indice);
    prefix_kernel<<<1, 1>>>();
    scatter_kernel<<<NN / 256, 256>>>(indice);
    prep_kernel<<<(GD * NN * DIMM) / 256, 256>>>(ih, ic, lk, lr, h_tensor, fc);
    for (int t = 0; t < 16; t++)
        step_mma_kernel<<<dim3(32, 4, 8), 256, SMEM_STEP>>>(t, indice, lb);
    gemm_fc_kernel<<<NN * KK / 128, NT, SMEM_STEP>>>(0);          // f_seq
    for (int g = 1; g <= 3; g++)
        gemm_fc_kernel<<<NN / 128, NT, SMEM_STEP>>>(g);           // y_last gates
    wx_gemm_kernel<<<dim3(64, 16), 256>>>(x, W_w, W_b);
    combine_kernel<<<NN, 256>>>(c_tensor, indice, out);
}

// round 10
// speedup vs baseline: 1.2727x; 1.2727x over previous
#include <cuda_runtime.h>
#include <cuda_fp16.h>
#include <math.h>
#include <cstdint>

#define NN   4096
#define KK   16
#define DIMM 256
#define RR   8192
#define GD   8

// ---- device scratch (static, no allocation) ----
__device__ int   g_hist[17];
__device__ int   g_off[17];
__device__ int   g_cnt[16];
__device__ int   g_sorted_orig[NN];
__device__ int   g_sorted_len[NN];
__device__ float g_Wx[NN * 1024];
__device__ float g_C[GD][NN * DIMM];           // c state fp32
__device__ __half g_Yf16[2][NN * KK * DIMM];   // gate-0 seq outputs, layout (t*NN+s)
__device__ __half g_Hfin[GD][NN * DIMM];       // final h per gd (fp16)
__device__ float g_fseq[NN * KK * DIMM];       // fc0 projection, layout (t*NN+s)
__device__ float g_ydot[3 * NN * DIMM];        // fc1..3 projections of y_last
// fp16 h/H state + weights
__device__ __half g_hf16[RR * DIMM];            // h_tensor (rounded)
__device__ __half g_Hf16[2][GD][NN * DIMM];     // H state (double buffered)
// packed weights: [gd][ntile4][chunk8] blocks of 256 n-rows x 64 k halves (K-major BT)
__device__ __half g_Bpf[8u * 4u * 8u * 16384u];
// packed fc weights: [gate4][256 n][512 k] fp16 (BT, K-major)
__device__ __half g_fcp[4u * 256u * 512u];

__device__ __forceinline__ float sigm(float x) { return 1.f / (1.f + expf(-x)); }

// ---- PTX helpers (non-'a' features only: cp.async, ldmatrix, mma.sync) ----
__device__ __forceinline__ uint32_t smem_u32(const void* p) {
    uint32_t a;
    asm("{ .reg .u64 t; cvta.to.shared.u64 t, %1; cvt.u32.u64 %0, t; }" : "=r"(a) : "l"(p));
    return a;
}
#define CP_ASYNC16(dst, src) \
    asm volatile("cp.async.cg.shared.global [%0], [%1], 16;" :: "r"(dst), "l"(src))
#define CP_COMMIT() asm volatile("cp.async.commit_group;" ::: "memory")
#define CP_WAIT(n)  asm volatile("cp.async.wait_group %0;" :: "n"(n) : "memory")

__device__ __forceinline__ void ldsm4(uint32_t* r, uint32_t addr) {
    asm volatile("ldmatrix.sync.aligned.m8n8.x4.shared.b16 {%0,%1,%2,%3}, [%4];"
                 : "=r"(r[0]), "=r"(r[1]), "=r"(r[2]), "=r"(r[3]) : "r"(addr));
}
__device__ __forceinline__ void mma_f16(float* c, const uint32_t* a, const uint32_t* b) {
    asm volatile("mma.sync.aligned.m16n8k16.row.col.f32.f16.f16.f32 "
                 "{%0,%1,%2,%3}, {%4,%5,%6,%7}, {%8,%9}, {%0,%1,%2,%3};"
                 : "+f"(c[0]), "+f"(c[1]), "+f"(c[2]), "+f"(c[3])
                 : "r"(a[0]), "r"(a[1]), "r"(a[2]), "r"(a[3]), "r"(b[0]), "r"(b[1]));
}

// ---------------- sorting by length (desc) ----------------
__global__ void zero_hist_kernel() { if (threadIdx.x < 17) g_hist[threadIdx.x] = 0; }

__global__ void len_hist_kernel(const int* __restrict__ indice) {
    int n = blockIdx.x * blockDim.x + threadIdx.x;
    if (n >= NN) return;
    int len = 0;
#pragma unroll
    for (int k = 0; k < KK; k++) len += (indice[n * KK + k] != -1);
    atomicAdd(&g_hist[len], 1);
}

__global__ void prefix_kernel() {
    if (threadIdx.x != 0 || blockIdx.x != 0) return;
    int run = 0;
    for (int l = 16; l >= 1; l--) { g_off[l] = run; run += g_hist[l]; }
    for (int t = 0; t < 16; t++) g_cnt[t] = g_off[t + 1] + g_hist[t + 1];
}

__global__ void scatter_kernel(const int* __restrict__ indice) {
    int n = blockIdx.x * blockDim.x + threadIdx.x;
    if (n >= NN) return;
    int len = 0;
#pragma unroll
    for (int k = 0; k < KK; k++) len += (indice[n * KK + k] != -1);
    int pos = atomicAdd(&g_off[len], 1);
    g_sorted_orig[pos] = n;
    g_sorted_len[pos]  = len;
}

// ------- prep: round h_tensor, pack weights (lstm + fc), init states -------
__global__ void prep_kernel(const float* __restrict__ ih, const float* __restrict__ ic,
                            const float* __restrict__ lk, const float* __restrict__ lr,
                            const float* __restrict__ h_tensor,
                            const float* __restrict__ fc_w) {
    int idx = blockIdx.x * blockDim.x + threadIdx.x;
    if (idx < RR * DIMM) {           // h_tensor round
        g_hf16[idx] = __float2half(h_tensor[idx]);
    }
    if (idx < 8 * 512 * 1024) {      // lstm weight pack: gate-interleaved, K-major BT blocks
        int gd = idx >> 19;
        int rem = idx & ((1 << 19) - 1);
        int kg = rem >> 10;          // 0..511
        int pc = rem & 1023;         // packed col: 4*j + q (q: 0=i,1=f,2=u,3=o)
        int oc = (pc & 3) * 256 + (pc >> 2);
        float w = (kg < 256) ? lk[((size_t)gd * 256 + kg) * 1024 + oc]
                             : lr[((size_t)gd * 256 + (kg - 256)) * 1024 + oc];
        int ntile = pc >> 8;         // 4 tiles of 256 packed cols
        int n     = pc & 255;
        int chunk = kg >> 6;
        int k     = kg & 63;
        size_t dst = ((size_t)(gd * 4 + ntile) * 8 + chunk) * 16384u + (size_t)n * 64 + k;
        g_Bpf[dst] = __float2half(w);
    }
    if (idx < 4 * 256 * 512) {       // fc weight pack: BT [gate][n][k]
        int g = idx >> 17;
        int rem = idx & ((1 << 17) - 1);
        int n = rem >> 9, k = rem & 511;
        g_fcp[idx] = __float2half(fc_w[((size_t)g * 512 + k) * 256 + n]);
    }
    if (idx < GD * NN * DIMM) {      // init H + C
        int j  = idx & (DIMM - 1);
        int gd = idx / (NN * DIMM);
        int r  = idx % (NN * DIMM);
        g_Hf16[0][gd][r] = __float2half(ih[gd * DIMM + j]);
        g_C[gd][r] = ic[gd * DIMM + j];
    }
}

// ---------------- W_x = x @ W_w + W_b ----------------
__global__ __launch_bounds__(256) void wx_gemm_kernel(
    const float* __restrict__ A, const float* __restrict__ B, const float* __restrict__ bias) {
    int m0 = blockIdx.x * 64, n0 = blockIdx.y * 64;
    int tid = threadIdx.x, tx = tid & 15, ty = tid >> 4;
    __shared__ __align__(16) float As[32][68];
    __shared__ __align__(16) float Bs[32][64];
    float acc[4][4];
#pragma unroll
    for (int u = 0; u < 4; u++) {
        float b = bias[n0 + tx * 4 + u];
#pragma unroll
        for (int i = 0; i < 4; i++) acc[i][u] = b;
    }
    for (int kb = 0; kb < 8; kb++) {
        int k0 = kb * 32;
        {
            int row = tid >> 2; int kp = (tid & 3) * 8;
            float4 v0 = *(const float4*)(A + (m0 + row) * 256 + k0 + kp);
            float4 v1 = *(const float4*)(A + (m0 + row) * 256 + k0 + kp + 4);
            As[kp + 0][row] = v0.x; As[kp + 1][row] = v0.y; As[kp + 2][row] = v0.z; As[kp + 3][row] = v0.w;
            As[kp + 4][row] = v1.x; As[kp + 5][row] = v1.y; As[kp + 6][row] = v1.z; As[kp + 7][row] = v1.w;
        }
#pragma unroll
        for (int jj = 0; jj < 8; jj++) {
            int l = tid + 256 * jj; int k = l >> 6; int c = l & 63;
            Bs[k][c] = B[(k0 + k) * 1024 + n0 + c];
        }
        __syncthreads();
#pragma unroll
        for (int kk = 0; kk < 32; kk++) {
            float4 av = *(const float4*)&As[kk][ty * 4];
            float4 bv = *(const float4*)&Bs[kk][tx * 4];
            float a[4] = {av.x, av.y, av.z, av.w};
            float b[4] = {bv.x, bv.y, bv.z, bv.w};
#pragma unroll
            for (int i = 0; i < 4; i++)
#pragma unroll
                for (int u = 0; u < 4; u++) acc[i][u] = fmaf(a[i], b[u], acc[i][u]);
        }
        __syncthreads();
    }
#pragma unroll
    for (int i = 0; i < 4; i++) {
        float4 v = make_float4(acc[i][0], acc[i][1], acc[i][2], acc[i][3]);
        *(float4*)&g_Wx[(m0 + ty * 4 + i) * 1024 + n0 + tx * 4] = v;
    }
}

// ---- HMMA recurrent step: CTA 128x256, 16 warps, warp 32x64, fp16, 3-deep pipe ----
#define SPA       18432                    // 128 rows x 144B
#define SPB       36864                    // 256 rows x 144B
#define BUF_B     (SPA + SPB)              // 55296
#define SM_CHILD  (3 * BUF_B)              // 165888
#define SMEM_STEP (3 * BUF_B + 512)        // 166400
#define NT        512

__global__ __launch_bounds__(NT, 1) void step_mma_kernel(
    int t, const int* __restrict__ indice, const float* __restrict__ lb) {
    extern __shared__ __align__(1024) char smem[];
    const int gd = blockIdx.z;
    const int ntile = blockIdx.y;            // 0..3 (256 packed cols each)
    const int Mact = g_cnt[t];
    const int m0 = blockIdx.x * 128;
    if (m0 >= Mact) return;
    const int tid = threadIdx.x;
    const int wid = tid >> 5, lane = tid & 31;
    const uint32_t sb = smem_u32(smem);
    int* childs = (int*)(smem + SM_CHILD);

    if (tid < 128) {
        int s = m0 + tid;
        int ci = 0;
        if (s < Mact) {
            int orig = g_sorted_orig[s];
            int len  = g_sorted_len[s];
            int tt = (gd & 1) ? (len - 1 - t) : t;
            ci = indice[orig * KK + tt];
        }
        childs[tid] = ci;
    }
    __syncthreads();

    const __half* Hin = &g_Hf16[t & 1][gd][0];
    const size_t bblk = (size_t)(gd * 4 + ntile) * 8;

    float acc[2][8][4];                      // warp tile 32x64: [mt2][nf8][quad]
#pragma unroll
    for (int mt = 0; mt < 2; mt++)
#pragma unroll
        for (int nf = 0; nf < 8; nf++)
#pragma unroll
            for (int u = 0; u < 4; u++) acc[mt][nf][u] = 0.f;

    const int mw = wid & 3, nw = wid >> 2;   // 4 x 4 warp grid
    const int m0w = mw * 32, n0w = nw * 64;
    const int am = lane >> 3, ar = lane & 7;

    auto stage = [&](int c) {
        uint32_t base = sb + (c % 3) * BUF_B;
        uint32_t aS = base;
        uint32_t bS = base + SPA;
#pragma unroll
        for (int i = 0; i < 2; i++) {       // A: 1024 segs of 16B
            int g = tid + i * NT;
            int row = g >> 3, seg = g & 7;
            const __half* src;
            if (c < 4) src = g_hf16 + (size_t)childs[row] * 256 + c * 64 + seg * 8;
            else       src = Hin + (size_t)(m0 + row) * 256 + (c - 4) * 64 + seg * 8;
            CP_ASYNC16(aS + row * 144 + seg * 16, src);
        }
        const __half* bw = g_Bpf + (bblk + c) * 16384u;
#pragma unroll
        for (int i = 0; i < 4; i++) {       // B: 2048 segs of 16B
            int g = tid + i * NT;
            int row = g >> 3, seg = g & 7;
            CP_ASYNC16(bS + row * 144 + seg * 16, bw + row * 64 + seg * 8);
        }
        CP_COMMIT();
    };

    auto compute = [&](int c) {
        uint32_t base = sb + (c % 3) * BUF_B;
        uint32_t aS = base;
        uint32_t bS = base + SPA;
#pragma unroll
        for (int ks = 0; ks < 4; ks++) {
            int k0 = ks * 16;
            uint32_t af[2][4];
            int arow_off = ((am & 1) ? 8 : 0) + ar;
            int akk = (k0 + ((am >= 2) ? 8 : 0)) * 2;
#pragma unroll
            for (int mt = 0; mt < 2; mt++) {
                uint32_t off = (uint32_t)(m0w + mt * 16 + arow_off) * 144 + akk;
                ldsm4(af[mt], aS + off);
            }
            int brow_off = ((am >= 2) ? 8 : 0) + ar;
            int bkk = (k0 + ((am & 1) ? 8 : 0)) * 2;
#pragma unroll
            for (int np = 0; np < 4; np++) {
                uint32_t off = (uint32_t)(n0w + np * 16 + brow_off) * 144 + bkk;
                uint32_t rb[4];
                ldsm4(rb, bS + off);
                uint32_t b0[2] = {rb[0], rb[1]}, b1[2] = {rb[2], rb[3]};
#pragma unroll
                for (int mt = 0; mt < 2; mt++) {
                    mma_f16(acc[mt][np * 2], af[mt], b0);
                    mma_f16(acc[mt][np * 2 + 1], af[mt], b1);
                }
            }
        }
    };

    stage(0);
    stage(1);
#pragma unroll
    for (int c = 0; c < 8; c++) {
        if (c == 7) { CP_WAIT(0); } else { CP_WAIT(1); }
        __syncthreads();
        if (c + 2 < 8) stage(c + 2);
        compute(c);
    }
    __syncthreads();

    // epilogue: accums -> smem (stride 264), then pointwise LSTM
    float* zs = (float*)smem;    // [128][264]
#pragma unroll
    for (int mt = 0; mt < 2; mt++)
#pragma unroll
        for (int nf = 0; nf < 8; nf++) {
            int row = m0w + mt * 16 + (lane >> 2);
            int col = n0w + nf * 8 + (lane & 3) * 2;
            zs[row * 264 + col]           = acc[mt][nf][0];
            zs[row * 264 + col + 1]       = acc[mt][nf][1];
            zs[(row + 8) * 264 + col]     = acc[mt][nf][2];
            zs[(row + 8) * 264 + col + 1] = acc[mt][nf][3];
        }
    __syncthreads();

    const int dsel = gd & 1;
    const bool isG0 = gd < 2;
    const int par = (t + 1) & 1;
    const int cntNext = (t < 15) ? g_cnt[t + 1] : 0;   // rows with len == t+1: s >= cntNext
#pragma unroll
    for (int i = 0; i < 16; i++) {
        int e = tid + i * NT;               // 128 rows x 64 dims
        int row = e >> 6, d = e & 63;
        int s = m0 + row;
        if (s < Mact) {
            int jb = ntile * 64 + d;
            float zi = zs[row * 264 + 4 * d + 0] + lb[gd * 1024 + jb];
            float zf = zs[row * 264 + 4 * d + 1] + lb[gd * 1024 + 256 + jb];
            float zu = zs[row * 264 + 4 * d + 2] + lb[gd * 1024 + 512 + jb];
            float zo = zs[row * 264 + 4 * d + 3] + lb[gd * 1024 + 768 + jb];
            size_t off = (size_t)s * DIMM + jb;
            float cnew = sigm(zf) * g_C[gd][off] + sigm(zi) * tanhf(zu);
            float hnew = sigm(zo) * tanhf(cnew);
            g_C[gd][off] = cnew;
            __half hh = __float2half(hnew);
            g_Hf16[par][gd][off] = hh;
            if (isG0) g_Yf16[dsel][((size_t)t * NN + s) * DIMM + jb] = hh;  // (t*NN+s) layout
            if (s >= cntNext) g_Hfin[gd][off] = hh;    // t == len-1: final h
        }
    }
}

// ---- generic HMMA fc GEMM: C[M,256] = [A0|A1][M,512] @ Bp^T, 16 warps, 32x64 ----
// mode 0: f_seq, grid (32, 16): y = t segment, prefix-trimmed by g_cnt[t].
// mode g in 1..3: y_last gate g (M=NN), grid (32, 1)
__global__ __launch_bounds__(NT, 1) void gemm_fc_kernel(int mode) {
    extern __shared__ __align__(1024) char smem[];
    const int tid = threadIdx.x;
    const int wid = tid >> 5, lane = tid & 31;
    const uint32_t sb = smem_u32(smem);

    const __half *A0, *A1, *Bp;
    float* Cout;
    size_t rbase;                       // global row base for this CTA
    if (mode == 0) {
        int tseg = blockIdx.y;
        int m0 = blockIdx.x * 128;
        if (m0 >= g_cnt[tseg]) return;  // prefix trim: only valid (t,s) rows
        rbase = (size_t)tseg * NN + m0;
        A0 = g_Yf16[0]; A1 = g_Yf16[1];
        Bp = g_fcp; Cout = g_fseq;
    } else {
        rbase = (size_t)blockIdx.x * 128;
        A0 = g_Hfin[2 * mode]; A1 = g_Hfin[2 * mode + 1];
        Bp = g_fcp + (size_t)mode * 131072u;
        Cout = g_ydot + (size_t)(mode - 1) * NN * DIMM;
    }

    float acc[2][8][4];
#pragma unroll
    for (int mt = 0; mt < 2; mt++)
#pragma unroll
        for (int nf = 0; nf < 8; nf++)
#pragma unroll
            for (int u = 0; u < 4; u++) acc[mt][nf][u] = 0.f;

    const int mw = wid & 3, nw = wid >> 2;
    const int m0w = mw * 32, n0w = nw * 64;
    const int am = lane >> 3, ar = lane & 7;

    auto stage = [&](int c) {
        uint32_t base = sb + (c % 3) * BUF_B;
        uint32_t aS = base;
        uint32_t bS = base + SPA;
#pragma unroll
        for (int i = 0; i < 2; i++) {
            int g = tid + i * NT;
            int row = g >> 3, seg = g & 7;
            const __half* src = (c < 4)
                ? A0 + (rbase + row) * 256 + c * 64 + seg * 8
                : A1 + (rbase + row) * 256 + (c - 4) * 64 + seg * 8;
            CP_ASYNC16(aS + row * 144 + seg * 16, src);
        }
#pragma unroll
        for (int i = 0; i < 4; i++) {
            int g = tid + i * NT;
            int row = g >> 3, seg = g & 7;   // row = n index, Bp stride 512
            CP_ASYNC16(bS + row * 144 + seg * 16, Bp + (size_t)row * 512 + c * 64 + seg * 8);
        }
        CP_COMMIT();
    };

    auto compute = [&](int c) {
        uint32_t base = sb + (c % 3) * BUF_B;
        uint32_t aS = base;
        uint32_t bS = base + SPA;
#pragma unroll
        for (int ks = 0; ks < 4; ks++) {
            int k0 = ks * 16;
            uint32_t af[2][4];
            int arow_off = ((am & 1) ? 8 : 0) + ar;
            int akk = (k0 + ((am >= 2) ? 8 : 0)) * 2;
#pragma unroll
            for (int mt = 0; mt < 2; mt++) {
                uint32_t off = (uint32_t)(m0w + mt * 16 + arow_off) * 144 + akk;
                ldsm4(af[mt], aS + off);
            }
            int brow_off = ((am >= 2) ? 8 : 0) + ar;
            int bkk = (k0 + ((am & 1) ? 8 : 0)) * 2;
#pragma unroll
            for (int np = 0; np < 4; np++) {
                uint32_t off = (uint32_t)(n0w + np * 16 + brow_off) * 144 + bkk;
                uint32_t rb[4];
                ldsm4(rb, bS + off);
                uint32_t b0[2] = {rb[0], rb[1]}, b1[2] = {rb[2], rb[3]};
#pragma unroll
                for (int mt = 0; mt < 2; mt++) {
                    mma_f16(acc[mt][np * 2], af[mt], b0);
                    mma_f16(acc[mt][np * 2 + 1], af[mt], b1);
                }
            }
        }
    };

    stage(0);
    stage(1);
#pragma unroll
    for (int c = 0; c < 8; c++) {
        if (c == 7) { CP_WAIT(0); } else { CP_WAIT(1); }
        __syncthreads();
        if (c + 2 < 8) stage(c + 2);
        compute(c);
    }
    __syncthreads();

    float* zs = (float*)smem;    // [128][264]
#pragma unroll
    for (int mt = 0; mt < 2; mt++)
#pragma unroll
        for (int nf = 0; nf < 8; nf++) {
            int row = m0w + mt * 16 + (lane >> 2);
            int col = n0w + nf * 8 + (lane & 3) * 2;
            zs[row * 264 + col]           = acc[mt][nf][0];
            zs[row * 264 + col + 1]       = acc[mt][nf][1];
            zs[(row + 8) * 264 + col]     = acc[mt][nf][2];
            zs[(row + 8) * 264 + col + 1] = acc[mt][nf][3];
        }
    __syncthreads();

#pragma unroll
    for (int i = 0; i < 16; i++) {          // 128 rows x 64 float4s
        int e = tid + i * NT;
        int row = e >> 6, q = e & 63;
        float4 v = make_float4(zs[row * 264 + q * 4], zs[row * 264 + q * 4 + 1],
                               zs[row * 264 + q * 4 + 2], zs[row * 264 + q * 4 + 3]);
        *(float4*)&Cout[(rbase + row) * 256 + q * 4] = v;
    }
}

// ---------------- final combine (light) ----------------
__global__ __launch_bounds__(256) void combine_kernel(
    const float* __restrict__ c_tensor, const int* __restrict__ indice,
    float* __restrict__ out) {
    int s = blockIdx.x;
    int j = threadIdx.x;
    int orig = g_sorted_orig[s];
    int len  = g_sorted_len[s];

    __shared__ int ciS[KK];
    if (j < KK) ciS[j] = (j < len) ? indice[orig * KK + j] : 0;
    __syncthreads();

    float Wf = g_Wx[orig * 1024 + j];
    float bf = 0.f;
    for (int t = 0; t < len; t++) {
        float fs = g_fseq[((size_t)t * NN + s) * DIMM + j];
        bf += sigm(Wf + fs) * c_tensor[(size_t)ciS[t] * DIMM + j];
    }

    float d0 = g_ydot[(size_t)0 * NN * DIMM + (size_t)s * DIMM + j];
    float d1 = g_ydot[(size_t)1 * NN * DIMM + (size_t)s * DIMM + j];
    float d2 = g_ydot[(size_t)2 * NN * DIMM + (size_t)s * DIMM + j];

    float Wi = g_Wx[orig * 1024 + 256 + j];
    float Wu = g_Wx[orig * 1024 + 512 + j];
    float Wo = g_Wx[orig * 1024 + 768 + j];
    float bi = sigm(d0 + Wi);
    float bu = tanhf(d1 + Wu);
    float bo = sigm(d2 + Wo);
    float nc = bi * bu + bf;
    float nh = bo * tanhf(nc);
    out[(size_t)orig * DIMM + j] = nh;
    out[(size_t)NN * DIMM + (size_t)orig * DIMM + j] = nc;
}

// ---------------- launch ----------------
extern "C" void kernel_launch(void* const* d_in, const int* in_sizes, int n_in,
                              void* d_out, int out_size) {
    const float* x        = (const float*)d_in[0];
    const float* h_tensor = (const float*)d_in[1];
    const float* c_tensor = (const float*)d_in[2];
    const int*   indice   = (const int*)d_in[3];
    const float* W_w      = (const float*)d_in[4];
    const float* W_b      = (const float*)d_in[5];
    const float* lk       = (const float*)d_in[6];
    const float* lr       = (const float*)d_in[7];
    const float* lb       = (const float*)d_in[8];
    const float* ih       = (const float*)d_in[9];
    const float* ic       = (const float*)d_in[10];
    const float* fc       = (const float*)d_in[11];
    float* out = (float*)d_out;

    cudaFuncSetAttribute(step_mma_kernel, cudaFuncAttributeMaxDynamicSharedMemorySize,
                         SMEM_STEP);
    cudaFuncSetAttribute(gemm_fc_kernel, cudaFuncAttributeMaxDynamicSharedMemorySize,
                         SMEM_STEP);

    zero_hist_kernel<<<1, 32>>>();
    len_hist_kernel<<<NN / 256, 256>>>(indice);
    prefix_kernel<<<1, 1>>>();
    scatter_kernel<<<NN / 256, 256>>>(indice);
    prep_kernel<<<(GD * NN * DIMM) / 256, 256>>>(ih, ic, lk, lr, h_tensor, fc);
    for (int t = 0; t < 16; t++)
        step_mma_kernel<<<dim3(32, 4, 8), NT, SMEM_STEP>>>(t, indice, lb);
    gemm_fc_kernel<<<dim3(32, 16), NT, SMEM_STEP>>>(0);           // f_seq (prefix-trimmed)
    for (int g = 1; g <= 3; g++)
        gemm_fc_kernel<<<dim3(32, 1), NT, SMEM_STEP>>>(g);        // y_last gates
    wx_gemm_kernel<<<dim3(64, 16), 256>>>(x, W_w, W_b);
    combine_kernel<<<NN, 256>>>(c_tensor, indice, out);
}

// round 11
// speedup vs baseline: 1.3387x; 1.0519x over previous
#include <cuda_runtime.h>
#include <cuda_fp16.h>
#include <math.h>
#include <cstdint>

#define NN   4096
#define KK   16
#define DIMM 256
#define RR   8192
#define GD   8

// ---- device scratch (static, no allocation) ----
__device__ int   g_hist[17];
__device__ int   g_off[17];
__device__ int   g_cnt[16];
__device__ int   g_sorted_orig[NN];
__device__ int   g_sorted_len[NN];
__device__ float g_Wx[NN * 1024];
__device__ float g_C[GD][NN * DIMM];           // c state fp32
__device__ __half g_Yf16[2][NN * KK * DIMM];   // gate-0 seq outputs, layout (t*NN+s)
__device__ __half g_Hfin[GD][NN * DIMM];       // final h per gd (fp16)
__device__ float g_fseq[NN * KK * DIMM];       // fc0 projection, layout (t*NN+s)
__device__ float g_ydot[3 * NN * DIMM];        // fc1..3 projections of y_last
// fp16 h/H state + weights
__device__ __half g_hf16[RR * DIMM];            // h_tensor (rounded)
__device__ __half g_Hf16[2][GD][NN * DIMM];     // H state (double buffered)
// packed weights: [gd][ntile8][chunk8] blocks of 128 n-rows x 64 k halves (K-major BT)
__device__ __half g_Bpf[8u * 8u * 8u * 8192u];
// packed fc weights: [gate4][256 n][512 k] fp16 (BT, K-major)
__device__ __half g_fcp[4u * 256u * 512u];

__device__ __forceinline__ float sigm(float x) { return 1.f / (1.f + expf(-x)); }

// ---- PTX helpers (non-'a' features only: cp.async, ldmatrix, mma.sync) ----
__device__ __forceinline__ uint32_t smem_u32(const void* p) {
    uint32_t a;
    asm("{ .reg .u64 t; cvta.to.shared.u64 t, %1; cvt.u32.u64 %0, t; }" : "=r"(a) : "l"(p));
    return a;
}
#define CP_ASYNC16(dst, src) \
    asm volatile("cp.async.cg.shared.global [%0], [%1], 16;" :: "r"(dst), "l"(src))
#define CP_COMMIT() asm volatile("cp.async.commit_group;" ::: "memory")
#define CP_WAIT(n)  asm volatile("cp.async.wait_group %0;" :: "n"(n) : "memory")

__device__ __forceinline__ void ldsm4(uint32_t* r, uint32_t addr) {
    asm volatile("ldmatrix.sync.aligned.m8n8.x4.shared.b16 {%0,%1,%2,%3}, [%4];"
                 : "=r"(r[0]), "=r"(r[1]), "=r"(r[2]), "=r"(r[3]) : "r"(addr));
}
__device__ __forceinline__ void mma_f16(float* c, const uint32_t* a, const uint32_t* b) {
    asm volatile("mma.sync.aligned.m16n8k16.row.col.f32.f16.f16.f32 "
                 "{%0,%1,%2,%3}, {%4,%5,%6,%7}, {%8,%9}, {%0,%1,%2,%3};"
                 : "+f"(c[0]), "+f"(c[1]), "+f"(c[2]), "+f"(c[3])
                 : "r"(a[0]), "r"(a[1]), "r"(a[2]), "r"(a[3]), "r"(b[0]), "r"(b[1]));
}

// ---------------- sorting by length (desc) ----------------
__global__ void zero_hist_kernel() { if (threadIdx.x < 17) g_hist[threadIdx.x] = 0; }

__global__ void len_hist_kernel(const int* __restrict__ indice) {
    int n = blockIdx.x * blockDim.x + threadIdx.x;
    if (n >= NN) return;
    int len = 0;
#pragma unroll
    for (int k = 0; k < KK; k++) len += (indice[n * KK + k] != -1);
    atomicAdd(&g_hist[len], 1);
}

__global__ void prefix_kernel() {
    if (threadIdx.x != 0 || blockIdx.x != 0) return;
    int run = 0;
    for (int l = 16; l >= 1; l--) { g_off[l] = run; run += g_hist[l]; }
    for (int t = 0; t < 16; t++) g_cnt[t] = g_off[t + 1] + g_hist[t + 1];
}

__global__ void scatter_kernel(const int* __restrict__ indice) {
    int n = blockIdx.x * blockDim.x + threadIdx.x;
    if (n >= NN) return;
    int len = 0;
#pragma unroll
    for (int k = 0; k < KK; k++) len += (indice[n * KK + k] != -1);
    int pos = atomicAdd(&g_off[len], 1);
    g_sorted_orig[pos] = n;
    g_sorted_len[pos]  = len;
}

// ------- prep: round h_tensor, pack weights (lstm + fc), init states -------
__global__ void prep_kernel(const float* __restrict__ ih, const float* __restrict__ ic,
                            const float* __restrict__ lk, const float* __restrict__ lr,
                            const float* __restrict__ h_tensor,
                            const float* __restrict__ fc_w) {
    int idx = blockIdx.x * blockDim.x + threadIdx.x;
    if (idx < RR * DIMM) {           // h_tensor round
        g_hf16[idx] = __float2half(h_tensor[idx]);
    }
    if (idx < 8 * 512 * 1024) {      // lstm weight pack: gate-interleaved, K-major BT blocks
        int gd = idx >> 19;
        int rem = idx & ((1 << 19) - 1);
        int kg = rem >> 10;          // 0..511
        int pc = rem & 1023;         // packed col: 4*j + q (q: 0=i,1=f,2=u,3=o)
        int oc = (pc & 3) * 256 + (pc >> 2);
        float w = (kg < 256) ? lk[((size_t)gd * 256 + kg) * 1024 + oc]
                             : lr[((size_t)gd * 256 + (kg - 256)) * 1024 + oc];
        int ntile = pc >> 7;         // 8 tiles of 128 packed cols
        int n     = pc & 127;
        int chunk = kg >> 6;
        int k     = kg & 63;
        size_t dst = ((size_t)(gd * 8 + ntile) * 8 + chunk) * 8192u + (size_t)n * 64 + k;
        g_Bpf[dst] = __float2half(w);
    }
    if (idx < 4 * 256 * 512) {       // fc weight pack: BT [gate][n][k]
        int g = idx >> 17;
        int rem = idx & ((1 << 17) - 1);
        int n = rem >> 9, k = rem & 511;
        g_fcp[idx] = __float2half(fc_w[((size_t)g * 512 + k) * 256 + n]);
    }
    if (idx < GD * NN * DIMM) {      // init H + C
        int j  = idx & (DIMM - 1);
        int gd = idx / (NN * DIMM);
        int r  = idx % (NN * DIMM);
        g_Hf16[0][gd][r] = __float2half(ih[gd * DIMM + j]);
        g_C[gd][r] = ic[gd * DIMM + j];
    }
}

// ---------------- W_x = x @ W_w + W_b ----------------
__global__ __launch_bounds__(256) void wx_gemm_kernel(
    const float* __restrict__ A, const float* __restrict__ B, const float* __restrict__ bias) {
    int m0 = blockIdx.x * 64, n0 = blockIdx.y * 64;
    int tid = threadIdx.x, tx = tid & 15, ty = tid >> 4;
    __shared__ __align__(16) float As[32][68];
    __shared__ __align__(16) float Bs[32][64];
    float acc[4][4];
#pragma unroll
    for (int u = 0; u < 4; u++) {
        float b = bias[n0 + tx * 4 + u];
#pragma unroll
        for (int i = 0; i < 4; i++) acc[i][u] = b;
    }
    for (int kb = 0; kb < 8; kb++) {
        int k0 = kb * 32;
        {
            int row = tid >> 2; int kp = (tid & 3) * 8;
            float4 v0 = *(const float4*)(A + (m0 + row) * 256 + k0 + kp);
            float4 v1 = *(const float4*)(A + (m0 + row) * 256 + k0 + kp + 4);
            As[kp + 0][row] = v0.x; As[kp + 1][row] = v0.y; As[kp + 2][row] = v0.z; As[kp + 3][row] = v0.w;
            As[kp + 4][row] = v1.x; As[kp + 5][row] = v1.y; As[kp + 6][row] = v1.z; As[kp + 7][row] = v1.w;
        }
#pragma unroll
        for (int jj = 0; jj < 8; jj++) {
            int l = tid + 256 * jj; int k = l >> 6; int c = l & 63;
            Bs[k][c] = B[(k0 + k) * 1024 + n0 + c];
        }
        __syncthreads();
#pragma unroll
        for (int kk = 0; kk < 32; kk++) {
            float4 av = *(const float4*)&As[kk][ty * 4];
            float4 bv = *(const float4*)&Bs[kk][tx * 4];
            float a[4] = {av.x, av.y, av.z, av.w};
            float b[4] = {bv.x, bv.y, bv.z, bv.w};
#pragma unroll
            for (int i = 0; i < 4; i++)
#pragma unroll
                for (int u = 0; u < 4; u++) acc[i][u] = fmaf(a[i], b[u], acc[i][u]);
        }
        __syncthreads();
    }
#pragma unroll
    for (int i = 0; i < 4; i++) {
        float4 v = make_float4(acc[i][0], acc[i][1], acc[i][2], acc[i][3]);
        *(float4*)&g_Wx[(m0 + ty * 4 + i) * 1024 + n0 + tx * 4] = v;
    }
}

// ---- HMMA recurrent step: CTA 128x128, 8 warps (32x64), 2 CTAs/SM, 3-deep pipe ----
#define SSPA      18432                    // A: 128 rows x 144B
#define SSPB      18432                    // B: 128 rows x 144B
#define SBUF      (SSPA + SSPB)            // 36864
#define SSM_CHILD (3 * SBUF)               // 110592
#define SMEM_STEPK (3 * SBUF + 512)        // 111104

__global__ __launch_bounds__(256, 2) void step_mma_kernel(
    int t, const int* __restrict__ indice, const float* __restrict__ lb) {
    extern __shared__ __align__(1024) char smem[];
    const int gd = blockIdx.z;
    const int ntile = blockIdx.y;            // 0..7 (128 packed cols = 32 dims each)
    const int Mact = g_cnt[t];
    const int m0 = blockIdx.x * 128;
    if (m0 >= Mact) return;
    const int tid = threadIdx.x;
    const int wid = tid >> 5, lane = tid & 31;
    const uint32_t sb = smem_u32(smem);
    int* childs = (int*)(smem + SSM_CHILD);

    if (tid < 128) {
        int s = m0 + tid;
        int ci = 0;
        if (s < Mact) {
            int orig = g_sorted_orig[s];
            int len  = g_sorted_len[s];
            int tt = (gd & 1) ? (len - 1 - t) : t;
            ci = indice[orig * KK + tt];
        }
        childs[tid] = ci;
    }
    __syncthreads();

    const __half* Hin = &g_Hf16[t & 1][gd][0];
    const size_t bblk = (size_t)(gd * 8 + ntile) * 8;

    float acc[2][8][4];                      // warp tile 32x64: [mt2][nf8][quad]
#pragma unroll
    for (int mt = 0; mt < 2; mt++)
#pragma unroll
        for (int nf = 0; nf < 8; nf++)
#pragma unroll
            for (int u = 0; u < 4; u++) acc[mt][nf][u] = 0.f;

    const int mw = wid & 3, nw = wid >> 2;   // 4 x 2 warp grid
    const int m0w = mw * 32, n0w = nw * 64;
    const int am = lane >> 3, ar = lane & 7;

    auto stage = [&](int c) {
        uint32_t base = sb + (c % 3) * SBUF;
        uint32_t aS = base;
        uint32_t bS = base + SSPA;
#pragma unroll
        for (int i = 0; i < 4; i++) {       // A: 1024 segs of 16B
            int g = tid + i * 256;
            int row = g >> 3, seg = g & 7;
            const __half* src;
            if (c < 4) src = g_hf16 + (size_t)childs[row] * 256 + c * 64 + seg * 8;
            else       src = Hin + (size_t)(m0 + row) * 256 + (c - 4) * 64 + seg * 8;
            CP_ASYNC16(aS + row * 144 + seg * 16, src);
        }
        const __half* bw = g_Bpf + (bblk + c) * 8192u;
#pragma unroll
        for (int i = 0; i < 4; i++) {       // B: 1024 segs of 16B
            int g = tid + i * 256;
            int row = g >> 3, seg = g & 7;
            CP_ASYNC16(bS + row * 144 + seg * 16, bw + row * 64 + seg * 8);
        }
        CP_COMMIT();
    };

    auto compute = [&](int c) {
        uint32_t base = sb + (c % 3) * SBUF;
        uint32_t aS = base;
        uint32_t bS = base + SSPA;
#pragma unroll
        for (int ks = 0; ks < 4; ks++) {
            int k0 = ks * 16;
            uint32_t af[2][4];
            int arow_off = ((am & 1) ? 8 : 0) + ar;
            int akk = (k0 + ((am >= 2) ? 8 : 0)) * 2;
#pragma unroll
            for (int mt = 0; mt < 2; mt++) {
                uint32_t off = (uint32_t)(m0w + mt * 16 + arow_off) * 144 + akk;
                ldsm4(af[mt], aS + off);
            }
            int brow_off = ((am >= 2) ? 8 : 0) + ar;
            int bkk = (k0 + ((am & 1) ? 8 : 0)) * 2;
#pragma unroll
            for (int np = 0; np < 4; np++) {
                uint32_t off = (uint32_t)(n0w + np * 16 + brow_off) * 144 + bkk;
                uint32_t rb[4];
                ldsm4(rb, bS + off);
                uint32_t b0[2] = {rb[0], rb[1]}, b1[2] = {rb[2], rb[3]};
#pragma unroll
                for (int mt = 0; mt < 2; mt++) {
                    mma_f16(acc[mt][np * 2], af[mt], b0);
                    mma_f16(acc[mt][np * 2 + 1], af[mt], b1);
                }
            }
        }
    };

    stage(0);
    stage(1);
#pragma unroll
    for (int c = 0; c < 8; c++) {
        if (c == 7) { CP_WAIT(0); } else { CP_WAIT(1); }
        __syncthreads();
        if (c + 2 < 8) stage(c + 2);
        compute(c);
    }
    __syncthreads();

    // epilogue: accums -> smem (stride 132), then pointwise LSTM
    float* zs = (float*)smem;    // [128][132]
#pragma unroll
    for (int mt = 0; mt < 2; mt++)
#pragma unroll
        for (int nf = 0; nf < 8; nf++) {
            int row = m0w + mt * 16 + (lane >> 2);
            int col = n0w + nf * 8 + (lane & 3) * 2;
            zs[row * 132 + col]           = acc[mt][nf][0];
            zs[row * 132 + col + 1]       = acc[mt][nf][1];
            zs[(row + 8) * 132 + col]     = acc[mt][nf][2];
            zs[(row + 8) * 132 + col + 1] = acc[mt][nf][3];
        }
    __syncthreads();

    const int dsel = gd & 1;
    const bool isG0 = gd < 2;
    const int par = (t + 1) & 1;
    const int cntNext = (t < 15) ? g_cnt[t + 1] : 0;   // rows with len == t+1: s >= cntNext
#pragma unroll
    for (int i = 0; i < 16; i++) {
        int e = tid + i * 256;              // 128 rows x 32 dims
        int row = e >> 5, d = e & 31;
        int s = m0 + row;
        if (s < Mact) {
            int jb = ntile * 32 + d;
            float zi = zs[row * 132 + 4 * d + 0] + lb[gd * 1024 + jb];
            float zf = zs[row * 132 + 4 * d + 1] + lb[gd * 1024 + 256 + jb];
            float zu = zs[row * 132 + 4 * d + 2] + lb[gd * 1024 + 512 + jb];
            float zo = zs[row * 132 + 4 * d + 3] + lb[gd * 1024 + 768 + jb];
            size_t off = (size_t)s * DIMM + jb;
            float cnew = sigm(zf) * g_C[gd][off] + sigm(zi) * tanhf(zu);
            float hnew = sigm(zo) * tanhf(cnew);
            g_C[gd][off] = cnew;
            __half hh = __float2half(hnew);
            g_Hf16[par][gd][off] = hh;
            if (isG0) g_Yf16[dsel][((size_t)t * NN + s) * DIMM + jb] = hh;  // (t*NN+s) layout
            if (s >= cntNext) g_Hfin[gd][off] = hh;    // t == len-1: final h
        }
    }
}

// ---- generic HMMA fc GEMM: C[M,256] = [A0|A1][M,512] @ Bp^T, 16 warps, 32x64 ----
#define SPA       18432                    // 128 rows x 144B
#define SPB       36864                    // 256 rows x 144B
#define BUF_B     (SPA + SPB)              // 55296
#define SMEM_FC   (3 * BUF_B + 512)        // 166400
#define NT        512

// mode 0: f_seq, grid (32, 16): y = t segment, prefix-trimmed by g_cnt[t].
// mode g in 1..3: y_last gate g (M=NN), grid (32, 1)
__global__ __launch_bounds__(NT, 1) void gemm_fc_kernel(int mode) {
    extern __shared__ __align__(1024) char smem[];
    const int tid = threadIdx.x;
    const int wid = tid >> 5, lane = tid & 31;
    const uint32_t sb = smem_u32(smem);

    const __half *A0, *A1, *Bp;
    float* Cout;
    size_t rbase;                       // global row base for this CTA
    if (mode == 0) {
        int tseg = blockIdx.y;
        int m0 = blockIdx.x * 128;
        if (m0 >= g_cnt[tseg]) return;  // prefix trim: only valid (t,s) rows
        rbase = (size_t)tseg * NN + m0;
        A0 = g_Yf16[0]; A1 = g_Yf16[1];
        Bp = g_fcp; Cout = g_fseq;
    } else {
        rbase = (size_t)blockIdx.x * 128;
        A0 = g_Hfin[2 * mode]; A1 = g_Hfin[2 * mode + 1];
        Bp = g_fcp + (size_t)mode * 131072u;
        Cout = g_ydot + (size_t)(mode - 1) * NN * DIMM;
    }

    float acc[2][8][4];
#pragma unroll
    for (int mt = 0; mt < 2; mt++)
#pragma unroll
        for (int nf = 0; nf < 8; nf++)
#pragma unroll
            for (int u = 0; u < 4; u++) acc[mt][nf][u] = 0.f;

    const int mw = wid & 3, nw = wid >> 2;
    const int m0w = mw * 32, n0w = nw * 64;
    const int am = lane >> 3, ar = lane & 7;

    auto stage = [&](int c) {
        uint32_t base = sb + (c % 3) * BUF_B;
        uint32_t aS = base;
        uint32_t bS = base + SPA;
#pragma unroll
        for (int i = 0; i < 2; i++) {
            int g = tid + i * NT;
            int row = g >> 3, seg = g & 7;
            const __half* src = (c < 4)
                ? A0 + (rbase + row) * 256 + c * 64 + seg * 8
                : A1 + (rbase + row) * 256 + (c - 4) * 64 + seg * 8;
            CP_ASYNC16(aS + row * 144 + seg * 16, src);
        }
#pragma unroll
        for (int i = 0; i < 4; i++) {
            int g = tid + i * NT;
            int row = g >> 3, seg = g & 7;   // row = n index, Bp stride 512
            CP_ASYNC16(bS + row * 144 + seg * 16, Bp + (size_t)row * 512 + c * 64 + seg * 8);
        }
        CP_COMMIT();
    };

    auto compute = [&](int c) {
        uint32_t base = sb + (c % 3) * BUF_B;
        uint32_t aS = base;
        uint32_t bS = base + SPA;
#pragma unroll
        for (int ks = 0; ks < 4; ks++) {
            int k0 = ks * 16;
            uint32_t af[2][4];
            int arow_off = ((am & 1) ? 8 : 0) + ar;
            int akk = (k0 + ((am >= 2) ? 8 : 0)) * 2;
#pragma unroll
            for (int mt = 0; mt < 2; mt++) {
                uint32_t off = (uint32_t)(m0w + mt * 16 + arow_off) * 144 + akk;
                ldsm4(af[mt], aS + off);
            }
            int brow_off = ((am >= 2) ? 8 : 0) + ar;
            int bkk = (k0 + ((am & 1) ? 8 : 0)) * 2;
#pragma unroll
            for (int np = 0; np < 4; np++) {
                uint32_t off = (uint32_t)(n0w + np * 16 + brow_off) * 144 + bkk;
                uint32_t rb[4];
                ldsm4(rb, bS + off);
                uint32_t b0[2] = {rb[0], rb[1]}, b1[2] = {rb[2], rb[3]};
#pragma unroll
                for (int mt = 0; mt < 2; mt++) {
                    mma_f16(acc[mt][np * 2], af[mt], b0);
                    mma_f16(acc[mt][np * 2 + 1], af[mt], b1);
                }
            }
        }
    };

    stage(0);
    stage(1);
#pragma unroll
    for (int c = 0; c < 8; c++) {
        if (c == 7) { CP_WAIT(0); } else { CP_WAIT(1); }
        __syncthreads();
        if (c + 2 < 8) stage(c + 2);
        compute(c);
    }
    __syncthreads();

    float* zs = (float*)smem;    // [128][264]
#pragma unroll
    for (int mt = 0; mt < 2; mt++)
#pragma unroll
        for (int nf = 0; nf < 8; nf++) {
            int row = m0w + mt * 16 + (lane >> 2);
            int col = n0w + nf * 8 + (lane & 3) * 2;
            zs[row * 264 + col]           = acc[mt][nf][0];
            zs[row * 264 + col + 1]       = acc[mt][nf][1];
            zs[(row + 8) * 264 + col]     = acc[mt][nf][2];
            zs[(row + 8) * 264 + col + 1] = acc[mt][nf][3];
        }
    __syncthreads();

#pragma unroll
    for (int i = 0; i < 16; i++) {          // 128 rows x 64 float4s
        int e = tid + i * NT;
        int row = e >> 6, q = e & 63;
        float4 v = make_float4(zs[row * 264 + q * 4], zs[row * 264 + q * 4 + 1],
                               zs[row * 264 + q * 4 + 2], zs[row * 264 + q * 4 + 3]);
        *(float4*)&Cout[(rbase + row) * 256 + q * 4] = v;
    }
}

// ---------------- final combine (light) ----------------
__global__ __launch_bounds__(256) void combine_kernel(
    const float* __restrict__ c_tensor, const int* __restrict__ indice,
    float* __restrict__ out) {
    int s = blockIdx.x;
    int j = threadIdx.x;
    int orig = g_sorted_orig[s];
    int len  = g_sorted_len[s];

    __shared__ int ciS[KK];
    if (j < KK) ciS[j] = (j < len) ? indice[orig * KK + j] : 0;
    __syncthreads();

    float Wf = g_Wx[orig * 1024 + j];
    float bf = 0.f;
    for (int t = 0; t < len; t++) {
        float fs = g_fseq[((size_t)t * NN + s) * DIMM + j];
        bf += sigm(Wf + fs) * c_tensor[(size_t)ciS[t] * DIMM + j];
    }

    float d0 = g_ydot[(size_t)0 * NN * DIMM + (size_t)s * DIMM + j];
    float d1 = g_ydot[(size_t)1 * NN * DIMM + (size_t)s * DIMM + j];
    float d2 = g_ydot[(size_t)2 * NN * DIMM + (size_t)s * DIMM + j];

    float Wi = g_Wx[orig * 1024 + 256 + j];
    float Wu = g_Wx[orig * 1024 + 512 + j];
    float Wo = g_Wx[orig * 1024 + 768 + j];
    float bi = sigm(d0 + Wi);
    float bu = tanhf(d1 + Wu);
    float bo = sigm(d2 + Wo);
    float nc = bi * bu + bf;
    float nh = bo * tanhf(nc);
    out[(size_t)orig * DIMM + j] = nh;
    out[(size_t)NN * DIMM + (size_t)orig * DIMM + j] = nc;
}

// ---------------- launch ----------------
extern "C" void kernel_launch(void* const* d_in, const int* in_sizes, int n_in,
                              void* d_out, int out_size) {
    const float* x        = (const float*)d_in[0];
    const float* h_tensor = (const float*)d_in[1];
    const float* c_tensor = (const float*)d_in[2];
    const int*   indice   = (const int*)d_in[3];
    const float* W_w      = (const float*)d_in[4];
    const float* W_b      = (const float*)d_in[5];
    const float* lk       = (const float*)d_in[6];
    const float* lr       = (const float*)d_in[7];
    const float* lb       = (const float*)d_in[8];
    const float* ih       = (const float*)d_in[9];
    const float* ic       = (const float*)d_in[10];
    const float* fc       = (const float*)d_in[11];
    float* out = (float*)d_out;

    cudaFuncSetAttribute(step_mma_kernel, cudaFuncAttributeMaxDynamicSharedMemorySize,
                         SMEM_STEPK);
    cudaFuncSetAttribute(gemm_fc_kernel, cudaFuncAttributeMaxDynamicSharedMemorySize,
                         SMEM_FC);

    zero_hist_kernel<<<1, 32>>>();
    len_hist_kernel<<<NN / 256, 256>>>(indice);
    prefix_kernel<<<1, 1>>>();
    scatter_kernel<<<NN / 256, 256>>>(indice);
    prep_kernel<<<(GD * NN * DIMM) / 256, 256>>>(ih, ic, lk, lr, h_tensor, fc);
    for (int t = 0; t < 16; t++)
        step_mma_kernel<<<dim3(32, 8, 8), 256, SMEM_STEPK>>>(t, indice, lb);
    gemm_fc_kernel<<<dim3(32, 16), NT, SMEM_FC>>>(0);             // f_seq (prefix-trimmed)
    for (int g = 1; g <= 3; g++)
        gemm_fc_kernel<<<dim3(32, 1), NT, SMEM_FC>>>(g);          // y_last gates
    wx_gemm_kernel<<<dim3(64, 16), 256>>>(x, W_w, W_b);
    combine_kernel<<<NN, 256>>>(c_tensor, indice, out);
}

// round 12
// speedup vs baseline: 1.4966x; 1.1180x over previous
#include <cuda_runtime.h>
#include <cuda_fp16.h>
#include <math.h>
#include <cstdint>

#define NN   4096
#define KK   16
#define DIMM 256
#define RR   8192
#define GD   8

// ---- device scratch (static, no allocation) ----
__device__ int   g_hist[17];
__device__ int   g_off[17];
__device__ int   g_cnt[16];
__device__ int   g_sorted_orig[NN];
__device__ int   g_sorted_len[NN];
__device__ float g_Wx[NN * 1024];
__device__ float g_C[GD][NN * DIMM];           // c state fp32
__device__ __half g_Yf16[2][NN * KK * DIMM];   // gate-0 seq outputs, layout (t*NN+s)
__device__ __half g_Hfin[GD][NN * DIMM];       // final h per gd (fp16)
__device__ float g_fseq[NN * KK * DIMM];       // fc0 projection, layout (t*NN+s)
__device__ float g_ydot[3 * NN * DIMM];        // fc1..3 projections of y_last
// fp16 h/H state + weights
__device__ __half g_hf16[RR * DIMM];            // h_tensor (rounded)
__device__ __half g_Hf16[2][GD][NN * DIMM];     // H state (double buffered)
__device__ __half g_xf16[NN * DIMM];            // x (rounded)
// packed weights: [gd][ntile8][chunk8] blocks of 128 n-rows x 64 k halves (K-major BT)
__device__ __half g_Bpf[8u * 8u * 8u * 8192u];
// packed fc weights: [gate4][256 n][512 k] fp16 (BT, K-major)
__device__ __half g_fcp[4u * 256u * 512u];
// packed W_w: [nt4][chunk4] blocks of 256 n-rows x 64 k halves
__device__ __half g_wwp[4u * 4u * 256u * 64u];

// ---- fast approx math (ex2/rcp approx, ~2^-22 error) ----
__device__ __forceinline__ float ex2f(float x) {
    float r; asm("ex2.approx.f32 %0, %1;" : "=f"(r) : "f"(x)); return r;
}
__device__ __forceinline__ float rcpf(float x) {
    float r; asm("rcp.approx.f32 %0, %1;" : "=f"(r) : "f"(x)); return r;
}
__device__ __forceinline__ float sigm(float x) {
    return rcpf(1.f + ex2f(-1.4426950408889634f * x));
}
__device__ __forceinline__ float tanh_fast(float x) {
    return 1.f - 2.f * rcpf(1.f + ex2f(2.8853900817779268f * x));
}

// ---- PTX helpers (non-'a' features only: cp.async, ldmatrix, mma.sync) ----
__device__ __forceinline__ uint32_t smem_u32(const void* p) {
    uint32_t a;
    asm("{ .reg .u64 t; cvta.to.shared.u64 t, %1; cvt.u32.u64 %0, t; }" : "=r"(a) : "l"(p));
    return a;
}
#define CP_ASYNC16(dst, src) \
    asm volatile("cp.async.cg.shared.global [%0], [%1], 16;" :: "r"(dst), "l"(src))
#define CP_COMMIT() asm volatile("cp.async.commit_group;" ::: "memory")
#define CP_WAIT(n)  asm volatile("cp.async.wait_group %0;" :: "n"(n) : "memory")

__device__ __forceinline__ void ldsm4(uint32_t* r, uint32_t addr) {
    asm volatile("ldmatrix.sync.aligned.m8n8.x4.shared.b16 {%0,%1,%2,%3}, [%4];"
                 : "=r"(r[0]), "=r"(r[1]), "=r"(r[2]), "=r"(r[3]) : "r"(addr));
}
__device__ __forceinline__ void mma_f16(float* c, const uint32_t* a, const uint32_t* b) {
    asm volatile("mma.sync.aligned.m16n8k16.row.col.f32.f16.f16.f32 "
                 "{%0,%1,%2,%3}, {%4,%5,%6,%7}, {%8,%9}, {%0,%1,%2,%3};"
                 : "+f"(c[0]), "+f"(c[1]), "+f"(c[2]), "+f"(c[3])
                 : "r"(a[0]), "r"(a[1]), "r"(a[2]), "r"(a[3]), "r"(b[0]), "r"(b[1]));
}

// ---------------- sorting by length (desc) ----------------
__global__ void zero_hist_kernel() { if (threadIdx.x < 17) g_hist[threadIdx.x] = 0; }

__global__ void len_hist_kernel(const int* __restrict__ indice) {
    int n = blockIdx.x * blockDim.x + threadIdx.x;
    if (n >= NN) return;
    int len = 0;
#pragma unroll
    for (int k = 0; k < KK; k++) len += (indice[n * KK + k] != -1);
    atomicAdd(&g_hist[len], 1);
}

__global__ void prefix_kernel() {
    if (threadIdx.x != 0 || blockIdx.x != 0) return;
    int run = 0;
    for (int l = 16; l >= 1; l--) { g_off[l] = run; run += g_hist[l]; }
    for (int t = 0; t < 16; t++) g_cnt[t] = g_off[t + 1] + g_hist[t + 1];
}

__global__ void scatter_kernel(const int* __restrict__ indice) {
    int n = blockIdx.x * blockDim.x + threadIdx.x;
    if (n >= NN) return;
    int len = 0;
#pragma unroll
    for (int k = 0; k < KK; k++) len += (indice[n * KK + k] != -1);
    int pos = atomicAdd(&g_off[len], 1);
    g_sorted_orig[pos] = n;
    g_sorted_len[pos]  = len;
}

// ------- prep: round h/x, pack weights (lstm + fc + wx), init states -------
__global__ void prep_kernel(const float* __restrict__ ih, const float* __restrict__ ic,
                            const float* __restrict__ lk, const float* __restrict__ lr,
                            const float* __restrict__ h_tensor,
                            const float* __restrict__ fc_w,
                            const float* __restrict__ x, const float* __restrict__ W_w) {
    int idx = blockIdx.x * blockDim.x + threadIdx.x;
    if (idx < RR * DIMM) {           // h_tensor round
        g_hf16[idx] = __float2half(h_tensor[idx]);
    }
    if (idx < NN * DIMM) {           // x round
        g_xf16[idx] = __float2half(x[idx]);
    }
    if (idx < 8 * 512 * 1024) {      // lstm weight pack: gate-interleaved, K-major BT blocks
        int gd = idx >> 19;
        int rem = idx & ((1 << 19) - 1);
        int kg = rem >> 10;          // 0..511
        int pc = rem & 1023;         // packed col: 4*j + q (q: 0=i,1=f,2=u,3=o)
        int oc = (pc & 3) * 256 + (pc >> 2);
        float w = (kg < 256) ? lk[((size_t)gd * 256 + kg) * 1024 + oc]
                             : lr[((size_t)gd * 256 + (kg - 256)) * 1024 + oc];
        int ntile = pc >> 7;         // 8 tiles of 128 packed cols
        int n     = pc & 127;
        int chunk = kg >> 6;
        int k     = kg & 63;
        size_t dst = ((size_t)(gd * 8 + ntile) * 8 + chunk) * 8192u + (size_t)n * 64 + k;
        g_Bpf[dst] = __float2half(w);
    }
    if (idx < 4 * 256 * 512) {       // fc weight pack: BT [gate][n][k]
        int g = idx >> 17;
        int rem = idx & ((1 << 17) - 1);
        int n = rem >> 9, k = rem & 511;
        g_fcp[idx] = __float2half(fc_w[((size_t)g * 512 + k) * 256 + n]);
    }
    if (idx < 4 * 4 * 256 * 64) {    // W_w pack: [nt][chunk][n][k]
        int k = idx & 63;
        int n = (idx >> 6) & 255;
        int chunk = (idx >> 14) & 3;
        int nt = idx >> 16;
        g_wwp[idx] = __float2half(W_w[((size_t)(chunk * 64 + k)) * 1024 + nt * 256 + n]);
    }
    if (idx < GD * NN * DIMM) {      // init H + C
        int j  = idx & (DIMM - 1);
        int gd = idx / (NN * DIMM);
        int r  = idx % (NN * DIMM);
        g_Hf16[0][gd][r] = __float2half(ih[gd * DIMM + j]);
        g_C[gd][r] = ic[gd * DIMM + j];
    }
}

// ---- HMMA recurrent step: CTA 128x128, 8 warps (32x64), 2 CTAs/SM, 3-deep pipe ----
#define SSPA      18432                    // A: 128 rows x 144B
#define SSPB      18432                    // B: 128 rows x 144B
#define SBUF      (SSPA + SSPB)            // 36864
#define SSM_CHILD (3 * SBUF)               // 110592
#define SMEM_STEPK (3 * SBUF + 512)        // 111104

__global__ __launch_bounds__(256, 2) void step_mma_kernel(
    int t, const int* __restrict__ indice, const float* __restrict__ lb) {
    extern __shared__ __align__(1024) char smem[];
    const int gd = blockIdx.z;
    const int ntile = blockIdx.y;            // 0..7 (128 packed cols = 32 dims each)
    const int Mact = g_cnt[t];
    const int m0 = blockIdx.x * 128;
    if (m0 >= Mact) return;
    const int tid = threadIdx.x;
    const int wid = tid >> 5, lane = tid & 31;
    const uint32_t sb = smem_u32(smem);
    int* childs = (int*)(smem + SSM_CHILD);

    if (tid < 128) {
        int s = m0 + tid;
        int ci = 0;
        if (s < Mact) {
            int orig = g_sorted_orig[s];
            int len  = g_sorted_len[s];
            int tt = (gd & 1) ? (len - 1 - t) : t;
            ci = indice[orig * KK + tt];
        }
        childs[tid] = ci;
    }
    __syncthreads();

    const __half* Hin = &g_Hf16[t & 1][gd][0];
    const size_t bblk = (size_t)(gd * 8 + ntile) * 8;

    float acc[2][8][4];                      // warp tile 32x64: [mt2][nf8][quad]
#pragma unroll
    for (int mt = 0; mt < 2; mt++)
#pragma unroll
        for (int nf = 0; nf < 8; nf++)
#pragma unroll
            for (int u = 0; u < 4; u++) acc[mt][nf][u] = 0.f;

    const int mw = wid & 3, nw = wid >> 2;   // 4 x 2 warp grid
    const int m0w = mw * 32, n0w = nw * 64;
    const int am = lane >> 3, ar = lane & 7;

    auto stage = [&](int c) {
        uint32_t base = sb + (c % 3) * SBUF;
        uint32_t aS = base;
        uint32_t bS = base + SSPA;
#pragma unroll
        for (int i = 0; i < 4; i++) {       // A: 1024 segs of 16B
            int g = tid + i * 256;
            int row = g >> 3, seg = g & 7;
            const __half* src;
            if (c < 4) src = g_hf16 + (size_t)childs[row] * 256 + c * 64 + seg * 8;
            else       src = Hin + (size_t)(m0 + row) * 256 + (c - 4) * 64 + seg * 8;
            CP_ASYNC16(aS + row * 144 + seg * 16, src);
        }
        const __half* bw = g_Bpf + (bblk + c) * 8192u;
#pragma unroll
        for (int i = 0; i < 4; i++) {       // B: 1024 segs of 16B
            int g = tid + i * 256;
            int row = g >> 3, seg = g & 7;
            CP_ASYNC16(bS + row * 144 + seg * 16, bw + row * 64 + seg * 8);
        }
        CP_COMMIT();
    };

    auto compute = [&](int c) {
        uint32_t base = sb + (c % 3) * SBUF;
        uint32_t aS = base;
        uint32_t bS = base + SSPA;
#pragma unroll
        for (int ks = 0; ks < 4; ks++) {
            int k0 = ks * 16;
            uint32_t af[2][4];
            int arow_off = ((am & 1) ? 8 : 0) + ar;
            int akk = (k0 + ((am >= 2) ? 8 : 0)) * 2;
#pragma unroll
            for (int mt = 0; mt < 2; mt++) {
                uint32_t off = (uint32_t)(m0w + mt * 16 + arow_off) * 144 + akk;
                ldsm4(af[mt], aS + off);
            }
            int brow_off = ((am >= 2) ? 8 : 0) + ar;
            int bkk = (k0 + ((am & 1) ? 8 : 0)) * 2;
#pragma unroll
            for (int np = 0; np < 4; np++) {
                uint32_t off = (uint32_t)(n0w + np * 16 + brow_off) * 144 + bkk;
                uint32_t rb[4];
                ldsm4(rb, bS + off);
                uint32_t b0[2] = {rb[0], rb[1]}, b1[2] = {rb[2], rb[3]};
#pragma unroll
                for (int mt = 0; mt < 2; mt++) {
                    mma_f16(acc[mt][np * 2], af[mt], b0);
                    mma_f16(acc[mt][np * 2 + 1], af[mt], b1);
                }
            }
        }
    };

    stage(0);
    stage(1);
#pragma unroll
    for (int c = 0; c < 8; c++) {
        if (c == 7) { CP_WAIT(0); } else { CP_WAIT(1); }
        __syncthreads();
        if (c + 2 < 8) stage(c + 2);
        compute(c);
    }
    __syncthreads();

    // epilogue: accums -> smem (stride 132), then pointwise LSTM
    float* zs = (float*)smem;    // [128][132]
#pragma unroll
    for (int mt = 0; mt < 2; mt++)
#pragma unroll
        for (int nf = 0; nf < 8; nf++) {
            int row = m0w + mt * 16 + (lane >> 2);
            int col = n0w + nf * 8 + (lane & 3) * 2;
            zs[row * 132 + col]           = acc[mt][nf][0];
            zs[row * 132 + col + 1]       = acc[mt][nf][1];
            zs[(row + 8) * 132 + col]     = acc[mt][nf][2];
            zs[(row + 8) * 132 + col + 1] = acc[mt][nf][3];
        }
    __syncthreads();

    const int dsel = gd & 1;
    const bool isG0 = gd < 2;
    const int par = (t + 1) & 1;
    const int cntNext = (t < 15) ? g_cnt[t + 1] : 0;   // rows with len == t+1: s >= cntNext
#pragma unroll
    for (int i = 0; i < 16; i++) {
        int e = tid + i * 256;              // 128 rows x 32 dims
        int row = e >> 5, d = e & 31;
        int s = m0 + row;
        if (s < Mact) {
            int jb = ntile * 32 + d;
            float zi = zs[row * 132 + 4 * d + 0] + lb[gd * 1024 + jb];
            float zf = zs[row * 132 + 4 * d + 1] + lb[gd * 1024 + 256 + jb];
            float zu = zs[row * 132 + 4 * d + 2] + lb[gd * 1024 + 512 + jb];
            float zo = zs[row * 132 + 4 * d + 3] + lb[gd * 1024 + 768 + jb];
            size_t off = (size_t)s * DIMM + jb;
            float cnew = sigm(zf) * g_C[gd][off] + sigm(zi) * tanh_fast(zu);
            float hnew = sigm(zo) * tanh_fast(cnew);
            g_C[gd][off] = cnew;
            __half hh = __float2half(hnew);
            g_Hf16[par][gd][off] = hh;
            if (isG0) g_Yf16[dsel][((size_t)t * NN + s) * DIMM + jb] = hh;  // (t*NN+s) layout
            if (s >= cntNext) g_Hfin[gd][off] = hh;    // t == len-1: final h
        }
    }
}

// ---- generic HMMA fc GEMM: C[M,256] = [A0|A1][M,512] @ Bp^T, 16 warps, 32x64 ----
#define SPA       18432                    // 128 rows x 144B
#define SPB       36864                    // 256 rows x 144B
#define BUF_B     (SPA + SPB)              // 55296
#define SMEM_FC   (3 * BUF_B + 512)        // 166400
#define NT        512

// mode 0: f_seq, grid (32, 16): y = t segment, prefix-trimmed by g_cnt[t].
// mode 9: y_last gates, grid (32, 3): gate = 1 + blockIdx.y
__global__ __launch_bounds__(NT, 1) void gemm_fc_kernel(int mode) {
    extern __shared__ __align__(1024) char smem[];
    const int tid = threadIdx.x;
    const int wid = tid >> 5, lane = tid & 31;
    const uint32_t sb = smem_u32(smem);

    int md = mode;
    if (md == 9) md = 1 + blockIdx.y;

    const __half *A0, *A1, *Bp;
    float* Cout;
    size_t rbase;                       // global row base for this CTA
    if (md == 0) {
        int tseg = blockIdx.y;
        int m0 = blockIdx.x * 128;
        if (m0 >= g_cnt[tseg]) return;  // prefix trim: only valid (t,s) rows
        rbase = (size_t)tseg * NN + m0;
        A0 = g_Yf16[0]; A1 = g_Yf16[1];
        Bp = g_fcp; Cout = g_fseq;
    } else {
        rbase = (size_t)blockIdx.x * 128;
        A0 = g_Hfin[2 * md]; A1 = g_Hfin[2 * md + 1];
        Bp = g_fcp + (size_t)md * 131072u;
        Cout = g_ydot + (size_t)(md - 1) * NN * DIMM;
    }

    float acc[2][8][4];
#pragma unroll
    for (int mt = 0; mt < 2; mt++)
#pragma unroll
        for (int nf = 0; nf < 8; nf++)
#pragma unroll
            for (int u = 0; u < 4; u++) acc[mt][nf][u] = 0.f;

    const int mw = wid & 3, nw = wid >> 2;
    const int m0w = mw * 32, n0w = nw * 64;
    const int am = lane >> 3, ar = lane & 7;

    auto stage = [&](int c) {
        uint32_t base = sb + (c % 3) * BUF_B;
        uint32_t aS = base;
        uint32_t bS = base + SPA;
#pragma unroll
        for (int i = 0; i < 2; i++) {
            int g = tid + i * NT;
            int row = g >> 3, seg = g & 7;
            const __half* src = (c < 4)
                ? A0 + (rbase + row) * 256 + c * 64 + seg * 8
                : A1 + (rbase + row) * 256 + (c - 4) * 64 + seg * 8;
            CP_ASYNC16(aS + row * 144 + seg * 16, src);
        }
#pragma unroll
        for (int i = 0; i < 4; i++) {
            int g = tid + i * NT;
            int row = g >> 3, seg = g & 7;   // row = n index, Bp stride 512
            CP_ASYNC16(bS + row * 144 + seg * 16, Bp + (size_t)row * 512 + c * 64 + seg * 8);
        }
        CP_COMMIT();
    };

    auto compute = [&](int c) {
        uint32_t base = sb + (c % 3) * BUF_B;
        uint32_t aS = base;
        uint32_t bS = base + SPA;
#pragma unroll
        for (int ks = 0; ks < 4; ks++) {
            int k0 = ks * 16;
            uint32_t af[2][4];
            int arow_off = ((am & 1) ? 8 : 0) + ar;
            int akk = (k0 + ((am >= 2) ? 8 : 0)) * 2;
#pragma unroll
            for (int mt = 0; mt < 2; mt++) {
                uint32_t off = (uint32_t)(m0w + mt * 16 + arow_off) * 144 + akk;
                ldsm4(af[mt], aS + off);
            }
            int brow_off = ((am >= 2) ? 8 : 0) + ar;
            int bkk = (k0 + ((am & 1) ? 8 : 0)) * 2;
#pragma unroll
            for (int np = 0; np < 4; np++) {
                uint32_t off = (uint32_t)(n0w + np * 16 + brow_off) * 144 + bkk;
                uint32_t rb[4];
                ldsm4(rb, bS + off);
                uint32_t b0[2] = {rb[0], rb[1]}, b1[2] = {rb[2], rb[3]};
#pragma unroll
                for (int mt = 0; mt < 2; mt++) {
                    mma_f16(acc[mt][np * 2], af[mt], b0);
                    mma_f16(acc[mt][np * 2 + 1], af[mt], b1);
                }
            }
        }
    };

    stage(0);
    stage(1);
#pragma unroll
    for (int c = 0; c < 8; c++) {
        if (c == 7) { CP_WAIT(0); } else { CP_WAIT(1); }
        __syncthreads();
        if (c + 2 < 8) stage(c + 2);
        compute(c);
    }
    __syncthreads();

    float* zs = (float*)smem;    // [128][264]
#pragma unroll
    for (int mt = 0; mt < 2; mt++)
#pragma unroll
        for (int nf = 0; nf < 8; nf++) {
            int row = m0w + mt * 16 + (lane >> 2);
            int col = n0w + nf * 8 + (lane & 3) * 2;
            zs[row * 264 + col]           = acc[mt][nf][0];
            zs[row * 264 + col + 1]       = acc[mt][nf][1];
            zs[(row + 8) * 264 + col]     = acc[mt][nf][2];
            zs[(row + 8) * 264 + col + 1] = acc[mt][nf][3];
        }
    __syncthreads();

#pragma unroll
    for (int i = 0; i < 16; i++) {          // 128 rows x 64 float4s
        int e = tid + i * NT;
        int row = e >> 6, q = e & 63;
        float4 v = make_float4(zs[row * 264 + q * 4], zs[row * 264 + q * 4 + 1],
                               zs[row * 264 + q * 4 + 2], zs[row * 264 + q * 4 + 3]);
        *(float4*)&Cout[(rbase + row) * 256 + q * 4] = v;
    }
}

// ---- Wx HMMA GEMM: Wx[4096,1024] = x_f16 @ W_w^T + W_b ; grid (32, 4), K=256 ----
__global__ __launch_bounds__(NT, 1) void wx_mma_kernel(const float* __restrict__ W_b) {
    extern __shared__ __align__(1024) char smem[];
    const int tid = threadIdx.x;
    const int wid = tid >> 5, lane = tid & 31;
    const uint32_t sb = smem_u32(smem);
    const int m0 = blockIdx.x * 128;
    const int nt = blockIdx.y;              // col tile of 256

    float acc[2][8][4];
#pragma unroll
    for (int mt = 0; mt < 2; mt++)
#pragma unroll
        for (int nf = 0; nf < 8; nf++)
#pragma unroll
            for (int u = 0; u < 4; u++) acc[mt][nf][u] = 0.f;

    const int mw = wid & 3, nw = wid >> 2;
    const int m0w = mw * 32, n0w = nw * 64;
    const int am = lane >> 3, ar = lane & 7;

    auto stage = [&](int c) {
        uint32_t base = sb + (c % 3) * BUF_B;
        uint32_t aS = base;
        uint32_t bS = base + SPA;
#pragma unroll
        for (int i = 0; i < 2; i++) {
            int g = tid + i * NT;
            int row = g >> 3, seg = g & 7;
            CP_ASYNC16(aS + row * 144 + seg * 16,
                       g_xf16 + (size_t)(m0 + row) * 256 + c * 64 + seg * 8);
        }
        const __half* bw = g_wwp + (size_t)(nt * 4 + c) * 16384u;
#pragma unroll
        for (int i = 0; i < 4; i++) {
            int g = tid + i * NT;
            int row = g >> 3, seg = g & 7;
            CP_ASYNC16(bS + row * 144 + seg * 16, bw + (size_t)row * 64 + seg * 8);
        }
        CP_COMMIT();
    };

    auto compute = [&](int c) {
        uint32_t base = sb + (c % 3) * BUF_B;
        uint32_t aS = base;
        uint32_t bS = base + SPA;
#pragma unroll
        for (int ks = 0; ks < 4; ks++) {
            int k0 = ks * 16;
            uint32_t af[2][4];
            int arow_off = ((am & 1) ? 8 : 0) + ar;
            int akk = (k0 + ((am >= 2) ? 8 : 0)) * 2;
#pragma unroll
            for (int mt = 0; mt < 2; mt++) {
                uint32_t off = (uint32_t)(m0w + mt * 16 + arow_off) * 144 + akk;
                ldsm4(af[mt], aS + off);
            }
            int brow_off = ((am >= 2) ? 8 : 0) + ar;
            int bkk = (k0 + ((am & 1) ? 8 : 0)) * 2;
#pragma unroll
            for (int np = 0; np < 4; np++) {
                uint32_t off = (uint32_t)(n0w + np * 16 + brow_off) * 144 + bkk;
                uint32_t rb[4];
                ldsm4(rb, bS + off);
                uint32_t b0[2] = {rb[0], rb[1]}, b1[2] = {rb[2], rb[3]};
#pragma unroll
                for (int mt = 0; mt < 2; mt++) {
                    mma_f16(acc[mt][np * 2], af[mt], b0);
                    mma_f16(acc[mt][np * 2 + 1], af[mt], b1);
                }
            }
        }
    };

    stage(0);
    stage(1);
#pragma unroll
    for (int c = 0; c < 4; c++) {
        if (c == 3) { CP_WAIT(0); } else { CP_WAIT(1); }
        __syncthreads();
        if (c + 2 < 4) stage(c + 2);
        compute(c);
    }
    __syncthreads();

    float* zs = (float*)smem;    // [128][264]
#pragma unroll
    for (int mt = 0; mt < 2; mt++)
#pragma unroll
        for (int nf = 0; nf < 8; nf++) {
            int row = m0w + mt * 16 + (lane >> 2);
            int col = n0w + nf * 8 + (lane & 3) * 2;
            zs[row * 264 + col]           = acc[mt][nf][0];
            zs[row * 264 + col + 1]       = acc[mt][nf][1];
            zs[(row + 8) * 264 + col]     = acc[mt][nf][2];
            zs[(row + 8) * 264 + col + 1] = acc[mt][nf][3];
        }
    __syncthreads();

#pragma unroll
    for (int i = 0; i < 16; i++) {          // 128 rows x 64 float4s
        int e = tid + i * NT;
        int row = e >> 6, q = e & 63;
        float4 b = *(const float4*)&W_b[nt * 256 + q * 4];
        float4 v = make_float4(zs[row * 264 + q * 4] + b.x, zs[row * 264 + q * 4 + 1] + b.y,
                               zs[row * 264 + q * 4 + 2] + b.z, zs[row * 264 + q * 4 + 3] + b.w);
        *(float4*)&g_Wx[(size_t)(m0 + row) * 1024 + nt * 256 + q * 4] = v;
    }
}

// ---------------- final combine (light) ----------------
__global__ __launch_bounds__(256) void combine_kernel(
    const float* __restrict__ c_tensor, const int* __restrict__ indice,
    float* __restrict__ out) {
    int s = blockIdx.x;
    int j = threadIdx.x;
    int orig = g_sorted_orig[s];
    int len  = g_sorted_len[s];

    __shared__ int ciS[KK];
    if (j < KK) ciS[j] = (j < len) ? indice[orig * KK + j] : 0;
    __syncthreads();

    float Wf = g_Wx[orig * 1024 + j];
    float bf = 0.f;
    for (int t = 0; t < len; t++) {
        float fs = g_fseq[((size_t)t * NN + s) * DIMM + j];
        bf += sigm(Wf + fs) * c_tensor[(size_t)ciS[t] * DIMM + j];
    }

    float d0 = g_ydot[(size_t)0 * NN * DIMM + (size_t)s * DIMM + j];
    float d1 = g_ydot[(size_t)1 * NN * DIMM + (size_t)s * DIMM + j];
    float d2 = g_ydot[(size_t)2 * NN * DIMM + (size_t)s * DIMM + j];

    float Wi = g_Wx[orig * 1024 + 256 + j];
    float Wu = g_Wx[orig * 1024 + 512 + j];
    float Wo = g_Wx[orig * 1024 + 768 + j];
    float bi = sigm(d0 + Wi);
    float bu = tanh_fast(d1 + Wu);
    float bo = sigm(d2 + Wo);
    float nc = bi * bu + bf;
    float nh = bo * tanh_fast(nc);
    out[(size_t)orig * DIMM + j] = nh;
    out[(size_t)NN * DIMM + (size_t)orig * DIMM + j] = nc;
}

// ---------------- launch ----------------
extern "C" void kernel_launch(void* const* d_in, const int* in_sizes, int n_in,
                              void* d_out, int out_size) {
    const float* x        = (const float*)d_in[0];
    const float* h_tensor = (const float*)d_in[1];
    const float* c_tensor = (const float*)d_in[2];
    const int*   indice   = (const int*)d_in[3];
    const float* W_w      = (const float*)d_in[4];
    const float* W_b      = (const float*)d_in[5];
    const float* lk       = (const float*)d_in[6];
    const float* lr       = (const float*)d_in[7];
    const float* lb       = (const float*)d_in[8];
    const float* ih       = (const float*)d_in[9];
    const float* ic       = (const float*)d_in[10];
    const float* fc       = (const float*)d_in[11];
    float* out = (float*)d_out;

    cudaFuncSetAttribute(step_mma_kernel, cudaFuncAttributeMaxDynamicSharedMemorySize,
                         SMEM_STEPK);
    cudaFuncSetAttribute(gemm_fc_kernel, cudaFuncAttributeMaxDynamicSharedMemorySize,
                         SMEM_FC);
    cudaFuncSetAttribute(wx_mma_kernel, cudaFuncAttributeMaxDynamicSharedMemorySize,
                         SMEM_FC);

    zero_hist_kernel<<<1, 32>>>();
    len_hist_kernel<<<NN / 256, 256>>>(indice);
    prefix_kernel<<<1, 1>>>();
    scatter_kernel<<<NN / 256, 256>>>(indice);
    prep_kernel<<<(GD * NN * DIMM) / 256, 256>>>(ih, ic, lk, lr, h_tensor, fc, x, W_w);
    for (int t = 0; t < 16; t++)
        step_mma_kernel<<<dim3(32, 8, 8), 256, SMEM_STEPK>>>(t, indice, lb);
    gemm_fc_kernel<<<dim3(32, 16), NT, SMEM_FC>>>(0);             // f_seq (prefix-trimmed)
    gemm_fc_kernel<<<dim3(32, 3), NT, SMEM_FC>>>(9);              // y_last gates 1..3
    wx_mma_kernel<<<dim3(32, 4), NT, SMEM_FC>>>(W_b);             // Wx (fp16 HMMA)
    combine_kernel<<<NN, 256>>>(c_tensor, indice, out);
}

// round 13
// speedup vs baseline: 1.6298x; 1.0890x over previous
#include <cuda_runtime.h>
#include <cuda_fp16.h>
#include <math.h>
#include <cstdint>

#define NN   4096
#define KK   16
#define DIMM 256
#define RR   8192
#define GD   8

// ---- device scratch (static, no allocation) ----
__device__ int   g_hist[17];
__device__ int   g_off[17];
__device__ int   g_cnt[16];
__device__ int   g_done[16 * 8 * 32];          // [t][gd][mtile] ntile-completion counters
__device__ int   g_sorted_orig[NN];
__device__ int   g_sorted_len[NN];
__device__ float g_Wx[NN * 1024];
__device__ float g_C[GD][NN * DIMM];           // c state fp32
__device__ __half g_Yf16[2][NN * KK * DIMM];   // gate-0 seq outputs, layout (t*NN+s)
__device__ __half g_Hfin[GD][NN * DIMM];       // final h per gd (fp16)
__device__ float g_fseq[NN * KK * DIMM];       // fc0 projection, layout (t*NN+s)
__device__ float g_ydot[3 * NN * DIMM];        // fc1..3 projections of y_last
// fp16 h/H state + weights
__device__ __half g_hf16[RR * DIMM];            // h_tensor (rounded)
__device__ __half g_Hf16[2][GD][NN * DIMM];     // H state (double buffered)
__device__ __half g_xf16[NN * DIMM];            // x (rounded)
// packed weights: [gd][ntile8][chunk8] blocks of 128 n-rows x 64 k halves (K-major BT)
__device__ __half g_Bpf[8u * 8u * 8u * 8192u];
// packed fc weights: [gate4][256 n][512 k] fp16 (BT, K-major)
__device__ __half g_fcp[4u * 256u * 512u];
// packed W_w: [nt4][chunk4] blocks of 256 n-rows x 64 k halves
__device__ __half g_wwp[4u * 4u * 256u * 64u];

// ---- fast approx math (ex2/rcp approx, ~2^-22 error) ----
__device__ __forceinline__ float ex2f(float x) {
    float r; asm("ex2.approx.f32 %0, %1;" : "=f"(r) : "f"(x)); return r;
}
__device__ __forceinline__ float rcpf(float x) {
    float r; asm("rcp.approx.f32 %0, %1;" : "=f"(r) : "f"(x)); return r;
}
__device__ __forceinline__ float sigm(float x) {
    return rcpf(1.f + ex2f(-1.4426950408889634f * x));
}
__device__ __forceinline__ float tanh_fast(float x) {
    return 1.f - 2.f * rcpf(1.f + ex2f(2.8853900817779268f * x));
}

// ---- PTX helpers (non-'a' features only: cp.async, ldmatrix, mma.sync) ----
__device__ __forceinline__ uint32_t smem_u32(const void* p) {
    uint32_t a;
    asm("{ .reg .u64 t; cvta.to.shared.u64 t, %1; cvt.u32.u64 %0, t; }" : "=r"(a) : "l"(p));
    return a;
}
#define CP_ASYNC16(dst, src) \
    asm volatile("cp.async.cg.shared.global [%0], [%1], 16;" :: "r"(dst), "l"(src))
#define CP_COMMIT() asm volatile("cp.async.commit_group;" ::: "memory")
#define CP_WAIT(n)  asm volatile("cp.async.wait_group %0;" :: "n"(n) : "memory")

__device__ __forceinline__ void ldsm4(uint32_t* r, uint32_t addr) {
    asm volatile("ldmatrix.sync.aligned.m8n8.x4.shared.b16 {%0,%1,%2,%3}, [%4];"
                 : "=r"(r[0]), "=r"(r[1]), "=r"(r[2]), "=r"(r[3]) : "r"(addr));
}
__device__ __forceinline__ void mma_f16(float* c, const uint32_t* a, const uint32_t* b) {
    asm volatile("mma.sync.aligned.m16n8k16.row.col.f32.f16.f16.f32 "
                 "{%0,%1,%2,%3}, {%4,%5,%6,%7}, {%8,%9}, {%0,%1,%2,%3};"
                 : "+f"(c[0]), "+f"(c[1]), "+f"(c[2]), "+f"(c[3])
                 : "r"(a[0]), "r"(a[1]), "r"(a[2]), "r"(a[3]), "r"(b[0]), "r"(b[1]));
}

// ---------------- sorting by length (desc) ----------------
__global__ void zero_hist_kernel() { if (threadIdx.x < 17) g_hist[threadIdx.x] = 0; }

__global__ void len_hist_kernel(const int* __restrict__ indice) {
    int n = blockIdx.x * blockDim.x + threadIdx.x;
    if (n >= NN) return;
    int len = 0;
#pragma unroll
    for (int k = 0; k < KK; k++) len += (indice[n * KK + k] != -1);
    atomicAdd(&g_hist[len], 1);
}

__global__ void prefix_kernel() {
    if (threadIdx.x != 0 || blockIdx.x != 0) return;
    int run = 0;
    for (int l = 16; l >= 1; l--) { g_off[l] = run; run += g_hist[l]; }
    for (int t = 0; t < 16; t++) g_cnt[t] = g_off[t + 1] + g_hist[t + 1];
}

__global__ void scatter_kernel(const int* __restrict__ indice) {
    int n = blockIdx.x * blockDim.x + threadIdx.x;
    if (n >= NN) return;
    int len = 0;
#pragma unroll
    for (int k = 0; k < KK; k++) len += (indice[n * KK + k] != -1);
    int pos = atomicAdd(&g_off[len], 1);
    g_sorted_orig[pos] = n;
    g_sorted_len[pos]  = len;
}

// ------- prep: round h/x, pack weights (lstm + fc + wx), init states, zero flags -------
__global__ void prep_kernel(const float* __restrict__ ih, const float* __restrict__ ic,
                            const float* __restrict__ lk, const float* __restrict__ lr,
                            const float* __restrict__ h_tensor,
                            const float* __restrict__ fc_w,
                            const float* __restrict__ x, const float* __restrict__ W_w) {
    int idx = blockIdx.x * blockDim.x + threadIdx.x;
    if (idx < 16 * 8 * 32) {         // zero step-dependency flags (every call: graph replay)
        g_done[idx] = 0;
    }
    if (idx < RR * DIMM) {           // h_tensor round
        g_hf16[idx] = __float2half(h_tensor[idx]);
    }
    if (idx < NN * DIMM) {           // x round
        g_xf16[idx] = __float2half(x[idx]);
    }
    if (idx < 8 * 512 * 1024) {      // lstm weight pack: gate-interleaved, K-major BT blocks
        int gd = idx >> 19;
        int rem = idx & ((1 << 19) - 1);
        int kg = rem >> 10;          // 0..511
        int pc = rem & 1023;         // packed col: 4*j + q (q: 0=i,1=f,2=u,3=o)
        int oc = (pc & 3) * 256 + (pc >> 2);
        float w = (kg < 256) ? lk[((size_t)gd * 256 + kg) * 1024 + oc]
                             : lr[((size_t)gd * 256 + (kg - 256)) * 1024 + oc];
        int ntile = pc >> 7;         // 8 tiles of 128 packed cols
        int n     = pc & 127;
        int chunk = kg >> 6;
        int k     = kg & 63;
        size_t dst = ((size_t)(gd * 8 + ntile) * 8 + chunk) * 8192u + (size_t)n * 64 + k;
        g_Bpf[dst] = __float2half(w);
    }
    if (idx < 4 * 256 * 512) {       // fc weight pack: BT [gate][n][k]
        int g = idx >> 17;
        int rem = idx & ((1 << 17) - 1);
        int n = rem >> 9, k = rem & 511;
        g_fcp[idx] = __float2half(fc_w[((size_t)g * 512 + k) * 256 + n]);
    }
    if (idx < 4 * 4 * 256 * 64) {    // W_w pack: [nt][chunk][n][k]
        int k = idx & 63;
        int n = (idx >> 6) & 255;
        int chunk = (idx >> 14) & 3;
        int nt = idx >> 16;
        g_wwp[idx] = __float2half(W_w[((size_t)(chunk * 64 + k)) * 1024 + nt * 256 + n]);
    }
    if (idx < GD * NN * DIMM) {      // init H + C
        int j  = idx & (DIMM - 1);
        int gd = idx / (NN * DIMM);
        int r  = idx % (NN * DIMM);
        g_Hf16[0][gd][r] = __float2half(ih[gd * DIMM + j]);
        g_C[gd][r] = ic[gd * DIMM + j];
    }
}

// ---- HMMA recurrent steps, ALL 16 FUSED: CTA 128x128, 8 warps, 2 CTAs/SM ----
// bid = t*2048 + mtile*64 + gd*8 + ntile  (t ascending => producers have smaller bid)
#define SSPA      18432                    // A: 128 rows x 144B
#define SSPB      18432                    // B: 128 rows x 144B
#define SBUF      (SSPA + SSPB)            // 36864
#define SSM_CHILD (3 * SBUF)               // 110592
#define SMEM_STEPK (3 * SBUF + 512)        // 111104

__global__ __launch_bounds__(256, 2) void step_mma_kernel(
    const int* __restrict__ indice, const float* __restrict__ lb) {
    extern __shared__ __align__(1024) char smem[];
    const int bid   = blockIdx.x;
    const int t     = bid >> 11;
    const int rem   = bid & 2047;
    const int mtile = rem >> 6;
    const int gd    = (rem >> 3) & 7;
    const int ntile = rem & 7;               // 128 packed cols = 32 dims
    const int Mact  = g_cnt[t];
    const int m0    = mtile * 128;
    if (m0 >= Mact) return;
    const int tid = threadIdx.x;
    const int wid = tid >> 5, lane = tid & 31;
    const uint32_t sb = smem_u32(smem);
    int* childs = (int*)(smem + SSM_CHILD);

    if (tid < 128) {
        int s = m0 + tid;
        int ci = 0;
        if (s < Mact) {
            int orig = g_sorted_orig[s];
            int len  = g_sorted_len[s];
            int tt = (gd & 1) ? (len - 1 - t) : t;
            ci = indice[orig * KK + tt];
        }
        childs[tid] = ci;
    }
    // wait for step t-1 of (gd, mtile): all 8 ntile producers done
    if (t > 0) {
        if (tid == 0) {
            const int* flag = &g_done[(((t - 1) * 8 + gd) << 5) + mtile];
            int v;
            do {
                asm volatile("ld.acquire.gpu.global.s32 %0, [%1];" : "=r"(v) : "l"(flag));
            } while (v < 8);
        }
        __syncthreads();
    } else {
        __syncthreads();
    }

    const __half* Hin = &g_Hf16[t & 1][gd][0];
    const size_t bblk = (size_t)(gd * 8 + ntile) * 8;

    float acc[2][8][4];                      // warp tile 32x64: [mt2][nf8][quad]
#pragma unroll
    for (int mt = 0; mt < 2; mt++)
#pragma unroll
        for (int nf = 0; nf < 8; nf++)
#pragma unroll
            for (int u = 0; u < 4; u++) acc[mt][nf][u] = 0.f;

    const int mw = wid & 3, nw = wid >> 2;   // 4 x 2 warp grid
    const int m0w = mw * 32, n0w = nw * 64;
    const int am = lane >> 3, ar = lane & 7;

    auto stage = [&](int c) {
        uint32_t base = sb + (c % 3) * SBUF;
        uint32_t aS = base;
        uint32_t bS = base + SSPA;
#pragma unroll
        for (int i = 0; i < 4; i++) {       // A: 1024 segs of 16B
            int g = tid + i * 256;
            int row = g >> 3, seg = g & 7;
            const __half* src;
            if (c < 4) src = g_hf16 + (size_t)childs[row] * 256 + c * 64 + seg * 8;
            else       src = Hin + (size_t)(m0 + row) * 256 + (c - 4) * 64 + seg * 8;
            CP_ASYNC16(aS + row * 144 + seg * 16, src);
        }
        const __half* bw = g_Bpf + (bblk + c) * 8192u;
#pragma unroll
        for (int i = 0; i < 4; i++) {       // B: 1024 segs of 16B
            int g = tid + i * 256;
            int row = g >> 3, seg = g & 7;
            CP_ASYNC16(bS + row * 144 + seg * 16, bw + row * 64 + seg * 8);
        }
        CP_COMMIT();
    };

    auto compute = [&](int c) {
        uint32_t base = sb + (c % 3) * SBUF;
        uint32_t aS = base;
        uint32_t bS = base + SSPA;
#pragma unroll
        for (int ks = 0; ks < 4; ks++) {
            int k0 = ks * 16;
            uint32_t af[2][4];
            int arow_off = ((am & 1) ? 8 : 0) + ar;
            int akk = (k0 + ((am >= 2) ? 8 : 0)) * 2;
#pragma unroll
            for (int mt = 0; mt < 2; mt++) {
                uint32_t off = (uint32_t)(m0w + mt * 16 + arow_off) * 144 + akk;
                ldsm4(af[mt], aS + off);
            }
            int brow_off = ((am >= 2) ? 8 : 0) + ar;
            int bkk = (k0 + ((am & 1) ? 8 : 0)) * 2;
#pragma unroll
            for (int np = 0; np < 4; np++) {
                uint32_t off = (uint32_t)(n0w + np * 16 + brow_off) * 144 + bkk;
                uint32_t rb[4];
                ldsm4(rb, bS + off);
                uint32_t b0[2] = {rb[0], rb[1]}, b1[2] = {rb[2], rb[3]};
#pragma unroll
                for (int mt = 0; mt < 2; mt++) {
                    mma_f16(acc[mt][np * 2], af[mt], b0);
                    mma_f16(acc[mt][np * 2 + 1], af[mt], b1);
                }
            }
        }
    };

    stage(0);
    stage(1);
#pragma unroll
    for (int c = 0; c < 8; c++) {
        if (c == 7) { CP_WAIT(0); } else { CP_WAIT(1); }
        __syncthreads();
        if (c + 2 < 8) stage(c + 2);
        compute(c);
    }
    __syncthreads();

    // epilogue: accums -> smem (stride 132), then pointwise LSTM
    float* zs = (float*)smem;    // [128][132]
#pragma unroll
    for (int mt = 0; mt < 2; mt++)
#pragma unroll
        for (int nf = 0; nf < 8; nf++) {
            int row = m0w + mt * 16 + (lane >> 2);
            int col = n0w + nf * 8 + (lane & 3) * 2;
            zs[row * 132 + col]           = acc[mt][nf][0];
            zs[row * 132 + col + 1]       = acc[mt][nf][1];
            zs[(row + 8) * 132 + col]     = acc[mt][nf][2];
            zs[(row + 8) * 132 + col + 1] = acc[mt][nf][3];
        }
    __syncthreads();

    const int dsel = gd & 1;
    const bool isG0 = gd < 2;
    const int par = (t + 1) & 1;
    const int cntNext = (t < 15) ? g_cnt[t + 1] : 0;   // rows with len == t+1: s >= cntNext
#pragma unroll
    for (int i = 0; i < 16; i++) {
        int e = tid + i * 256;              // 128 rows x 32 dims
        int row = e >> 5, d = e & 31;
        int s = m0 + row;
        if (s < Mact) {
            int jb = ntile * 32 + d;
            float zi = zs[row * 132 + 4 * d + 0] + lb[gd * 1024 + jb];
            float zf = zs[row * 132 + 4 * d + 1] + lb[gd * 1024 + 256 + jb];
            float zu = zs[row * 132 + 4 * d + 2] + lb[gd * 1024 + 512 + jb];
            float zo = zs[row * 132 + 4 * d + 3] + lb[gd * 1024 + 768 + jb];
            size_t off = (size_t)s * DIMM + jb;
            float cnew = sigm(zf) * g_C[gd][off] + sigm(zi) * tanh_fast(zu);
            float hnew = sigm(zo) * tanh_fast(cnew);
            g_C[gd][off] = cnew;
            __half hh = __float2half(hnew);
            g_Hf16[par][gd][off] = hh;
            if (isG0) g_Yf16[dsel][((size_t)t * NN + s) * DIMM + jb] = hh;  // (t*NN+s) layout
            if (s >= cntNext) g_Hfin[gd][off] = hh;    // t == len-1: final h
        }
    }

    // signal completion of (t, gd, mtile, ntile)
    __threadfence();
    __syncthreads();
    if (tid == 0) atomicAdd(&g_done[((t * 8 + gd) << 5) + mtile], 1);
}

// ---- generic HMMA fc GEMM: C[M,256] = [A0|A1][M,512] @ Bp^T, 16 warps, 32x64 ----
#define SPA       18432                    // 128 rows x 144B
#define SPB       36864                    // 256 rows x 144B
#define BUF_B     (SPA + SPB)              // 55296
#define SMEM_FC   (3 * BUF_B + 512)        // 166400
#define NT        512

// mode 0: f_seq, grid (32, 16): y = t segment, prefix-trimmed by g_cnt[t].
// mode 9: y_last gates, grid (32, 3): gate = 1 + blockIdx.y
__global__ __launch_bounds__(NT, 1) void gemm_fc_kernel(int mode) {
    extern __shared__ __align__(1024) char smem[];
    const int tid = threadIdx.x;
    const int wid = tid >> 5, lane = tid & 31;
    const uint32_t sb = smem_u32(smem);

    int md = mode;
    if (md == 9) md = 1 + blockIdx.y;

    const __half *A0, *A1, *Bp;
    float* Cout;
    size_t rbase;                       // global row base for this CTA
    if (md == 0) {
        int tseg = blockIdx.y;
        int m0 = blockIdx.x * 128;
        if (m0 >= g_cnt[tseg]) return;  // prefix trim: only valid (t,s) rows
        rbase = (size_t)tseg * NN + m0;
        A0 = g_Yf16[0]; A1 = g_Yf16[1];
        Bp = g_fcp; Cout = g_fseq;
    } else {
        rbase = (size_t)blockIdx.x * 128;
        A0 = g_Hfin[2 * md]; A1 = g_Hfin[2 * md + 1];
        Bp = g_fcp + (size_t)md * 131072u;
        Cout = g_ydot + (size_t)(md - 1) * NN * DIMM;
    }

    float acc[2][8][4];
#pragma unroll
    for (int mt = 0; mt < 2; mt++)
#pragma unroll
        for (int nf = 0; nf < 8; nf++)
#pragma unroll
            for (int u = 0; u < 4; u++) acc[mt][nf][u] = 0.f;

    const int mw = wid & 3, nw = wid >> 2;
    const int m0w = mw * 32, n0w = nw * 64;
    const int am = lane >> 3, ar = lane & 7;

    auto stage = [&](int c) {
        uint32_t base = sb + (c % 3) * BUF_B;
        uint32_t aS = base;
        uint32_t bS = base + SPA;
#pragma unroll
        for (int i = 0; i < 2; i++) {
            int g = tid + i * NT;
            int row = g >> 3, seg = g & 7;
            const __half* src = (c < 4)
                ? A0 + (rbase + row) * 256 + c * 64 + seg * 8
                : A1 + (rbase + row) * 256 + (c - 4) * 64 + seg * 8;
            CP_ASYNC16(aS + row * 144 + seg * 16, src);
        }
#pragma unroll
        for (int i = 0; i < 4; i++) {
            int g = tid + i * NT;
            int row = g >> 3, seg = g & 7;   // row = n index, Bp stride 512
            CP_ASYNC16(bS + row * 144 + seg * 16, Bp + (size_t)row * 512 + c * 64 + seg * 8);
        }
        CP_COMMIT();
    };

    auto compute = [&](int c) {
        uint32_t base = sb + (c % 3) * BUF_B;
        uint32_t aS = base;
        uint32_t bS = base + SPA;
#pragma unroll
        for (int ks = 0; ks < 4; ks++) {
            int k0 = ks * 16;
            uint32_t af[2][4];
            int arow_off = ((am & 1) ? 8 : 0) + ar;
            int akk = (k0 + ((am >= 2) ? 8 : 0)) * 2;
#pragma unroll
            for (int mt = 0; mt < 2; mt++) {
                uint32_t off = (uint32_t)(m0w + mt * 16 + arow_off) * 144 + akk;
                ldsm4(af[mt], aS + off);
            }
            int brow_off = ((am >= 2) ? 8 : 0) + ar;
            int bkk = (k0 + ((am & 1) ? 8 : 0)) * 2;
#pragma unroll
            for (int np = 0; np < 4; np++) {
                uint32_t off = (uint32_t)(n0w + np * 16 + brow_off) * 144 + bkk;
                uint32_t rb[4];
                ldsm4(rb, bS + off);
                uint32_t b0[2] = {rb[0], rb[1]}, b1[2] = {rb[2], rb[3]};
#pragma unroll
                for (int mt = 0; mt < 2; mt++) {
                    mma_f16(acc[mt][np * 2], af[mt], b0);
                    mma_f16(acc[mt][np * 2 + 1], af[mt], b1);
                }
            }
        }
    };

    stage(0);
    stage(1);
#pragma unroll
    for (int c = 0; c < 8; c++) {
        if (c == 7) { CP_WAIT(0); } else { CP_WAIT(1); }
        __syncthreads();
        if (c + 2 < 8) stage(c + 2);
        compute(c);
    }
    __syncthreads();

    float* zs = (float*)smem;    // [128][264]
#pragma unroll
    for (int mt = 0; mt < 2; mt++)
#pragma unroll
        for (int nf = 0; nf < 8; nf++) {
            int row = m0w + mt * 16 + (lane >> 2);
            int col = n0w + nf * 8 + (lane & 3) * 2;
            zs[row * 264 + col]           = acc[mt][nf][0];
            zs[row * 264 + col + 1]       = acc[mt][nf][1];
            zs[(row + 8) * 264 + col]     = acc[mt][nf][2];
            zs[(row + 8) * 264 + col + 1] = acc[mt][nf][3];
        }
    __syncthreads();

#pragma unroll
    for (int i = 0; i < 16; i++) {          // 128 rows x 64 float4s
        int e = tid + i * NT;
        int row = e >> 6, q = e & 63;
        float4 v = make_float4(zs[row * 264 + q * 4], zs[row * 264 + q * 4 + 1],
                               zs[row * 264 + q * 4 + 2], zs[row * 264 + q * 4 + 3]);
        *(float4*)&Cout[(rbase + row) * 256 + q * 4] = v;
    }
}

// ---- Wx HMMA GEMM: Wx[4096,1024] = x_f16 @ W_w^T + W_b ; grid (32, 4), K=256 ----
__global__ __launch_bounds__(NT, 1) void wx_mma_kernel(const float* __restrict__ W_b) {
    extern __shared__ __align__(1024) char smem[];
    const int tid = threadIdx.x;
    const int wid = tid >> 5, lane = tid & 31;
    const uint32_t sb = smem_u32(smem);
    const int m0 = blockIdx.x * 128;
    const int nt = blockIdx.y;              // col tile of 256

    float acc[2][8][4];
#pragma unroll
    for (int mt = 0; mt < 2; mt++)
#pragma unroll
        for (int nf = 0; nf < 8; nf++)
#pragma unroll
            for (int u = 0; u < 4; u++) acc[mt][nf][u] = 0.f;

    const int mw = wid & 3, nw = wid >> 2;
    const int m0w = mw * 32, n0w = nw * 64;
    const int am = lane >> 3, ar = lane & 7;

    auto stage = [&](int c) {
        uint32_t base = sb + (c % 3) * BUF_B;
        uint32_t aS = base;
        uint32_t bS = base + SPA;
#pragma unroll
        for (int i = 0; i < 2; i++) {
            int g = tid + i * NT;
            int row = g >> 3, seg = g & 7;
            CP_ASYNC16(aS + row * 144 + seg * 16,
                       g_xf16 + (size_t)(m0 + row) * 256 + c * 64 + seg * 8);
        }
        const __half* bw = g_wwp + (size_t)(nt * 4 + c) * 16384u;
#pragma unroll
        for (int i = 0; i < 4; i++) {
            int g = tid + i * NT;
            int row = g >> 3, seg = g & 7;
            CP_ASYNC16(bS + row * 144 + seg * 16, bw + (size_t)row * 64 + seg * 8);
        }
        CP_COMMIT();
    };

    auto compute = [&](int c) {
        uint32_t base = sb + (c % 3) * BUF_B;
        uint32_t aS = base;
        uint32_t bS = base + SPA;
#pragma unroll
        for (int ks = 0; ks < 4; ks++) {
            int k0 = ks * 16;
            uint32_t af[2][4];
            int arow_off = ((am & 1) ? 8 : 0) + ar;
            int akk = (k0 + ((am >= 2) ? 8 : 0)) * 2;
#pragma unroll
            for (int mt = 0; mt < 2; mt++) {
                uint32_t off = (uint32_t)(m0w + mt * 16 + arow_off) * 144 + akk;
                ldsm4(af[mt], aS + off);
            }
            int brow_off = ((am >= 2) ? 8 : 0) + ar;
            int bkk = (k0 + ((am & 1) ? 8 : 0)) * 2;
#pragma unroll
            for (int np = 0; np < 4; np++) {
                uint32_t off = (uint32_t)(n0w + np * 16 + brow_off) * 144 + bkk;
                uint32_t rb[4];
                ldsm4(rb, bS + off);
                uint32_t b0[2] = {rb[0], rb[1]}, b1[2] = {rb[2], rb[3]};
#pragma unroll
                for (int mt = 0; mt < 2; mt++) {
                    mma_f16(acc[mt][np * 2], af[mt], b0);
                    mma_f16(acc[mt][np * 2 + 1], af[mt], b1);
                }
            }
        }
    };

    stage(0);
    stage(1);
#pragma unroll
    for (int c = 0; c < 4; c++) {
        if (c == 3) { CP_WAIT(0); } else { CP_WAIT(1); }
        __syncthreads();
        if (c + 2 < 4) stage(c + 2);
        compute(c);
    }
    __syncthreads();

    float* zs = (float*)smem;    // [128][264]
#pragma unroll
    for (int mt = 0; mt < 2; mt++)
#pragma unroll
        for (int nf = 0; nf < 8; nf++) {
            int row = m0w + mt * 16 + (lane >> 2);
            int col = n0w + nf * 8 + (lane & 3) * 2;
            zs[row * 264 + col]           = acc[mt][nf][0];
            zs[row * 264 + col + 1]       = acc[mt][nf][1];
            zs[(row + 8) * 264 + col]     = acc[mt][nf][2];
            zs[(row + 8) * 264 + col + 1] = acc[mt][nf][3];
        }
    __syncthreads();

#pragma unroll
    for (int i = 0; i < 16; i++) {          // 128 rows x 64 float4s
        int e = tid + i * NT;
        int row = e >> 6, q = e & 63;
        float4 b = *(const float4*)&W_b[nt * 256 + q * 4];
        float4 v = make_float4(zs[row * 264 + q * 4] + b.x, zs[row * 264 + q * 4 + 1] + b.y,
                               zs[row * 264 + q * 4 + 2] + b.z, zs[row * 264 + q * 4 + 3] + b.w);
        *(float4*)&g_Wx[(size_t)(m0 + row) * 1024 + nt * 256 + q * 4] = v;
    }
}

// ---------------- final combine (light) ----------------
__global__ __launch_bounds__(256) void combine_kernel(
    const float* __restrict__ c_tensor, const int* __restrict__ indice,
    float* __restrict__ out) {
    int s = blockIdx.x;
    int j = threadIdx.x;
    int orig = g_sorted_orig[s];
    int len  = g_sorted_len[s];

    __shared__ int ciS[KK];
    if (j < KK) ciS[j] = (j < len) ? indice[orig * KK + j] : 0;
    __syncthreads();

    float Wf = g_Wx[orig * 1024 + j];
    float bf = 0.f;
    for (int t = 0; t < len; t++) {
        float fs = g_fseq[((size_t)t * NN + s) * DIMM + j];
        bf += sigm(Wf + fs) * c_tensor[(size_t)ciS[t] * DIMM + j];
    }

    float d0 = g_ydot[(size_t)0 * NN * DIMM + (size_t)s * DIMM + j];
    float d1 = g_ydot[(size_t)1 * NN * DIMM + (size_t)s * DIMM + j];
    float d2 = g_ydot[(size_t)2 * NN * DIMM + (size_t)s * DIMM + j];

    float Wi = g_Wx[orig * 1024 + 256 + j];
    float Wu = g_Wx[orig * 1024 + 512 + j];
    float Wo = g_Wx[orig * 1024 + 768 + j];
    float bi = sigm(d0 + Wi);
    float bu = tanh_fast(d1 + Wu);
    float bo = sigm(d2 + Wo);
    float nc = bi * bu + bf;
    float nh = bo * tanh_fast(nc);
    out[(size_t)orig * DIMM + j] = nh;
    out[(size_t)NN * DIMM + (size_t)orig * DIMM + j] = nc;
}

// ---------------- launch ----------------
extern "C" void kernel_launch(void* const* d_in, const int* in_sizes, int n_in,
                              void* d_out, int out_size) {
    const float* x        = (const float*)d_in[0];
    const float* h_tensor = (const float*)d_in[1];
    const float* c_tensor = (const float*)d_in[2];
    const int*   indice   = (const int*)d_in[3];
    const float* W_w      = (const float*)d_in[4];
    const float* W_b      = (const float*)d_in[5];
    const float* lk       = (const float*)d_in[6];
    const float* lr       = (const float*)d_in[7];
    const float* lb       = (const float*)d_in[8];
    const float* ih       = (const float*)d_in[9];
    const float* ic       = (const float*)d_in[10];
    const float* fc       = (const float*)d_in[11];
    float* out = (float*)d_out;

    cudaFuncSetAttribute(step_mma_kernel, cudaFuncAttributeMaxDynamicSharedMemorySize,
                         SMEM_STEPK);
    cudaFuncSetAttribute(gemm_fc_kernel, cudaFuncAttributeMaxDynamicSharedMemorySize,
                         SMEM_FC);
    cudaFuncSetAttribute(wx_mma_kernel, cudaFuncAttributeMaxDynamicSharedMemorySize,
                         SMEM_FC);

    zero_hist_kernel<<<1, 32>>>();
    len_hist_kernel<<<NN / 256, 256>>>(indice);
    prefix_kernel<<<1, 1>>>();
    scatter_kernel<<<NN / 256, 256>>>(indice);
    prep_kernel<<<(GD * NN * DIMM) / 256, 256>>>(ih, ic, lk, lr, h_tensor, fc, x, W_w);
    step_mma_kernel<<<16 * 2048, 256, SMEM_STEPK>>>(indice, lb);   // all 16 steps, fused
    gemm_fc_kernel<<<dim3(32, 16), NT, SMEM_FC>>>(0);             // f_seq (prefix-trimmed)
    gemm_fc_kernel<<<dim3(32, 3), NT, SMEM_FC>>>(9);              // y_last gates 1..3
    wx_mma_kernel<<<dim3(32, 4), NT, SMEM_FC>>>(W_b);             // Wx (fp16 HMMA)
    combine_kernel<<<NN, 256>>>(c_tensor, indice, out);
}